// round 8
// baseline (speedup 1.0000x reference)
#include <cuda_runtime.h>
#include <math.h>

typedef unsigned long long u64;
typedef ulonglong2 u64x2;

#define Hn   256
#define Wn   256
#define CIN  64
#define COUT 64
#define Bn   16

__device__ __forceinline__ u64 f2u(float lo, float hi) {
    u64 r; asm("mov.b64 %0, {%1,%2};" : "=l"(r) : "f"(lo), "f"(hi)); return r;
}
__device__ __forceinline__ float2 u2f(u64 v) {
    float2 r; asm("mov.b64 {%0,%1}, %2;" : "=f"(r.x), "=f"(r.y) : "l"(v)); return r;
}
__device__ __forceinline__ u64 ffma2(u64 a, u64 b, u64 c) {
    u64 d; asm("fma.rn.f32x2 %0, %1, %2, %3;" : "=l"(d) : "l"(a), "l"(b), "l"(c));
    return d;
}
__device__ __forceinline__ u64 fadd2(u64 a, u64 b) {
    u64 d; asm("add.rn.f32x2 %0, %1, %2;" : "=l"(d) : "l"(a), "l"(b));
    return d;
}
__device__ __forceinline__ u64 fsub2(u64 a, u64 b) {
    u64 nb = b ^ 0x8000000080000000ull;
    return fadd2(a, nb);
}
// (lo,hi) -> (hi, -lo)
__device__ __forceinline__ u64 swapneg(u64 v) {
    float2 f = u2f(v); return f2u(f.y, -f.x);
}

// Intermediate spectra, packed (re, im) in one u64
__device__ u64 g_X[Bn * CIN * 1024];
__device__ u64 g_S[Bn * COUT * 1024];

// ---------------------------------------------------------------------------
// Forward v3: per (b,i) block, 256x256 -> 32x32 modes.
// Quarter-folded row DFT (65 taps, kx-parity arrays) + h-folded column DFT.
// smem: cs[65][32] f2 | t4[256] f4 | xq[128][65] u64x2 | x64[128] u64 | D[256][32] u64
// ---------------------------------------------------------------------------
#define FWD_SMEM_BYTES (65*32*8 + 256*16 + 128*65*16 + 128*8 + 256*32*8)

__global__ __launch_bounds__(256, 1) void fwd_kernel(const float* __restrict__ x) {
    extern __shared__ char smraw[];
    float2* s_cs  = (float2*)smraw;                  // [w*32 + kx] = (c, -s)
    float4* s_t4  = (float4*)(s_cs + 65 * 32);       // [n] = (c, c, s, s)
    u64x2*  s_xq  = (u64x2*)(s_t4 + 256);            // [r*65 + w] = {(ee,om),(eo,op)}
    u64*    s_x64 = (u64*)(s_xq + 128 * 65);         // [r] = (xe64, xo64)
    u64*    s_D   = s_x64 + 128;                     // [h*32 + kx]

    const int t  = threadIdx.x;
    const int bi = blockIdx.x;
    const float* xp = x + (size_t)bi * (Hn * Wn);

    for (int idx = t; idx < 65 * 32; idx += 256) {
        int w = idx >> 5, kx = idx & 31;
        float sv, cv;
        sincospif(((w * kx) & 255) * (2.0f / 256.0f), &sv, &cv);
        s_cs[idx] = make_float2(cv, -sv);
    }
    {
        float sv, cv;
        sincospif(t * (2.0f / 256.0f), &sv, &cv);
        s_t4[t] = make_float4(cv, cv, sv, sv);
    }

    // stage-B mapping: warp = 8 kx-lanes x 4 row-lanes; thread = 4 rows x 4 kx
    const int warp = t >> 5, lane = t & 31;
    const int kxl = lane & 7, rg = lane >> 3;
    const int kx0 = kxl * 4;
    const int rbase = warp * 16 + rg;        // rows rbase + 4u, u=0..3

    const u64* cs64 = (const u64*)s_cs;

    __syncthreads();

    for (int c4 = 0; c4 < 2; ++c4) {
        const int h0 = c4 * 128;

        // ---- loader: quarter-fold 128 rows into s_xq / s_x64
        for (int idx = t; idx < 128 * 64; idx += 256) {
            int r = idx >> 6;
            int w = idx & 63;
            const float* row = xp + (size_t)(h0 + r) * Wn;
            if (w == 0) {
                float x0 = row[0], x128 = row[128];
                u64x2 v; v.x = f2u(x0 + x128, 0.f); v.y = f2u(x0 - x128, 0.f);
                s_xq[r * 65] = v;
                float a = row[64], b = row[192];
                s_x64[r] = f2u(a + b, a - b);
            } else {
                float xa = row[w], xb = row[256 - w];
                float xc = row[128 - w], xd = row[128 + w];
                u64x2 v;
                v.x = f2u(xa + xb + xc + xd, xa - xb - xc + xd);   // (ee, om)
                v.y = f2u(xa + xb - xc - xd, xa - xb + xc - xd);   // (eo, op)
                s_xq[r * 65 + w] = v;
            }
        }
        __syncthreads();

        // ---- stage B: D[r,kx] over 65 folded taps
        {
            u64 acc[4][4];
            #pragma unroll
            for (int u = 0; u < 4; ++u)
                #pragma unroll
                for (int k = 0; k < 4; ++k) acc[u][k] = 0ull;

            #pragma unroll 4
            for (int w = 0; w < 64; ++w) {
                u64x2 tw01 = *(const u64x2*)&cs64[w * 32 + kx0];
                u64x2 tw23 = *(const u64x2*)&cs64[w * 32 + kx0 + 2];
                #pragma unroll
                for (int u = 0; u < 4; ++u) {
                    u64x2 v = s_xq[(rbase + 4 * u) * 65 + w];
                    acc[u][0] = ffma2(v.x, tw01.x, acc[u][0]);
                    acc[u][1] = ffma2(v.y, tw01.y, acc[u][1]);
                    acc[u][2] = ffma2(v.x, tw23.x, acc[u][2]);
                    acc[u][3] = ffma2(v.y, tw23.y, acc[u][3]);
                }
            }
            {   // tap w = 64: raw (xe64, xo64) for all kx
                u64x2 tw01 = *(const u64x2*)&cs64[64 * 32 + kx0];
                u64x2 tw23 = *(const u64x2*)&cs64[64 * 32 + kx0 + 2];
                #pragma unroll
                for (int u = 0; u < 4; ++u) {
                    u64 v = s_x64[rbase + 4 * u];
                    acc[u][0] = ffma2(v, tw01.x, acc[u][0]);
                    acc[u][1] = ffma2(v, tw01.y, acc[u][1]);
                    acc[u][2] = ffma2(v, tw23.x, acc[u][2]);
                    acc[u][3] = ffma2(v, tw23.y, acc[u][3]);
                }
            }
            #pragma unroll
            for (int u = 0; u < 4; ++u) {
                u64* dst = &s_D[(h0 + rbase + 4 * u) * 32 + kx0];
                u64x2 p0; p0.x = acc[u][0]; p0.y = acc[u][1];
                u64x2 p1; p1.x = acc[u][2]; p1.y = acc[u][3];
                *(u64x2*)dst       = p0;
                *(u64x2*)(dst + 2) = p1;
            }
        }
        __syncthreads();
    }

    // ---- stage C: h-folded column transform.  thread = 2 ky x 2 kx
    {
        const int kxc = (t & 15) * 2;
        const int ky0 = (t >> 4) * 2;
        u64 X[2][2];
        X[0][0] = X[0][1] = X[1][0] = X[1][1] = 0ull;

        #pragma unroll 2
        for (int h = 1; h < 128; ++h) {
            u64x2 d  = *(const u64x2*)&s_D[h * 32 + kxc];
            u64x2 dm = *(const u64x2*)&s_D[(256 - h) * 32 + kxc];
            u64 ds0 = fadd2(d.x, dm.x), ds1 = fadd2(d.y, dm.y);
            u64 dq0 = swapneg(fsub2(d.x, dm.x));
            u64 dq1 = swapneg(fsub2(d.y, dm.y));
            u64x2 e0 = *(const u64x2*)&s_t4[(ky0 * h) & 255];
            u64x2 e1 = *(const u64x2*)&s_t4[((ky0 + 1) * h) & 255];
            X[0][0] = ffma2(ds0, e0.x, X[0][0]); X[0][0] = ffma2(dq0, e0.y, X[0][0]);
            X[0][1] = ffma2(ds1, e0.x, X[0][1]); X[0][1] = ffma2(dq1, e0.y, X[0][1]);
            X[1][0] = ffma2(ds0, e1.x, X[1][0]); X[1][0] = ffma2(dq0, e1.y, X[1][0]);
            X[1][1] = ffma2(ds1, e1.x, X[1][1]); X[1][1] = ffma2(dq1, e1.y, X[1][1]);
        }
        #pragma unroll
        for (int s = 0; s < 2; ++s) {       // singles h = 0, 128
            const int hs = s * 128;
            u64x2 d = *(const u64x2*)&s_D[hs * 32 + kxc];
            u64 dq0 = swapneg(d.x), dq1 = swapneg(d.y);
            u64x2 e0 = *(const u64x2*)&s_t4[(ky0 * hs) & 255];
            u64x2 e1 = *(const u64x2*)&s_t4[((ky0 + 1) * hs) & 255];
            X[0][0] = ffma2(d.x, e0.x, X[0][0]); X[0][0] = ffma2(dq0, e0.y, X[0][0]);
            X[0][1] = ffma2(d.y, e0.x, X[0][1]); X[0][1] = ffma2(dq1, e0.y, X[0][1]);
            X[1][0] = ffma2(d.x, e1.x, X[1][0]); X[1][0] = ffma2(dq0, e1.y, X[1][0]);
            X[1][1] = ffma2(d.y, e1.x, X[1][1]); X[1][1] = ffma2(dq1, e1.y, X[1][1]);
        }
        #pragma unroll
        for (int j = 0; j < 2; ++j)
            #pragma unroll
            for (int i = 0; i < 2; ++i)
                g_X[(size_t)bi * 1024 + (ky0 + j) * 32 + kxc + i] = X[j][i];
    }
}

// ---------------------------------------------------------------------------
// Mix (unchanged)
// ---------------------------------------------------------------------------
__global__ __launch_bounds__(256) void mix_kernel(const float* __restrict__ wts) {
    __shared__ float s_W[CIN * COUT];
    __shared__ u64   s_X[Bn * CIN];
    const int t = threadIdx.x;
    const int m = blockIdx.x;

    for (int e = t; e < CIN * COUT; e += 256)
        s_W[e] = wts[(size_t)e * 1024 + m];
    for (int e = t; e < Bn * CIN; e += 256)
        s_X[e] = g_X[(size_t)e * 1024 + m];
    __syncthreads();

    const int o  = t & 63;
    const int bq = t >> 6;
    u64 acc[4] = {0ull, 0ull, 0ull, 0ull};

    #pragma unroll 8
    for (int i = 0; i < CIN; ++i) {
        float wv = s_W[i * 64 + o];
        u64 wp = f2u(wv, wv);
        #pragma unroll
        for (int j = 0; j < 4; ++j)
            acc[j] = ffma2(s_X[(bq * 4 + j) * 64 + i], wp, acc[j]);
    }
    #pragma unroll
    for (int j = 0; j < 4; ++j)
        g_S[((size_t)(bq * 4 + j) * 64 + o) * 1024 + m] = acc[j];
}

// ---------------------------------------------------------------------------
// Inverse (unchanged)
// ---------------------------------------------------------------------------
#define INV_SMEM_BYTES (32*130*8 + 256*16 + 32*32*8 + 16*32*8)

__global__ __launch_bounds__(256) void inv_kernel(const float* __restrict__ bias,
                                                  float* __restrict__ out) {
    extern __shared__ char smraw[];
    float2* s_ci  = (float2*)smraw;
    float4* s_t4i = (float4*)(s_ci + 32 * 130);
    u64*    s_S   = (u64*)(s_t4i + 256);
    u64*    s_G   = s_S + 32 * 32;

    const int t  = threadIdx.x;
    const int bo = blockIdx.x;
    const int o  = bo & 63;

    for (int idx = t; idx < 32 * 129; idx += 256) {
        int kk = idx / 129;
        int w  = idx - kk * 129;
        float sv, cv;
        sincospif(((kk * w) & 255) * (2.0f / 256.0f), &sv, &cv);
        s_ci[kk * 130 + w] = make_float2(cv, sv);
    }
    {
        float sv, cv;
        sincospif(t * (2.0f / 256.0f), &sv, &cv);
        s_t4i[t] = make_float4(cv, sv, -sv, cv);
    }
    for (int e = t; e < 1024; e += 256) {
        float2 v  = u2f(g_S[(size_t)bo * 1024 + e]);
        float sc  = ((e & 31) == 0 ? 1.f : 2.f) * (1.f / 65536.f);
        s_S[e] = f2u(v.x * sc, v.y * sc);
    }
    const float bias_o = bias[o];
    __syncthreads();

    const int kx = t & 31, r2 = t >> 5;
    const int warp = t >> 5, lane = t & 31;
    const int wl = lane & 7, rl = lane >> 3;
    const int w0 = warp * 16 + wl * 2;

    const u64* ci64 = (const u64*)s_ci;
    float* yp = out + (size_t)bo * (Hn * Wn);

    for (int c = 0; c < 16; ++c) {
        const int hb = c * 16;
        {
            const int h1 = hb + r2, h2 = h1 + 8;
            u64 a1 = 0ull, a2 = 0ull;
            #pragma unroll 8
            for (int ky = 0; ky < 32; ++ky) {
                float2 sv = u2f(s_S[ky * 32 + kx]);
                u64 sxx = f2u(sv.x, sv.x);
                u64 syy = f2u(sv.y, sv.y);
                u64x2 e1 = *(const u64x2*)&s_t4i[(ky * h1) & 255];
                u64x2 e2 = *(const u64x2*)&s_t4i[(ky * h2) & 255];
                a1 = ffma2(sxx, e1.x, a1);
                a1 = ffma2(syy, e1.y, a1);
                a2 = ffma2(sxx, e2.x, a2);
                a2 = ffma2(syy, e2.y, a2);
            }
            s_G[r2 * 32 + kx]       = a1;
            s_G[(r2 + 8) * 32 + kx] = a2;
        }
        __syncthreads();
        {
            u64 acc[4][2];
            float aN[4];
            #pragma unroll
            for (int u = 0; u < 4; ++u) {
                acc[u][0] = acc[u][1] = 0ull; aN[u] = 0.f;
            }
            #pragma unroll 4
            for (int kk = 0; kk < 32; kk += 2) {
                u64x2 cs0 = *(const u64x2*)&ci64[kk * 130 + w0];
                u64x2 cs1 = *(const u64x2*)&ci64[(kk + 1) * 130 + w0];
                #pragma unroll
                for (int u = 0; u < 4; ++u) {
                    u64x2 gv = *(const u64x2*)&s_G[(u * 4 + rl) * 32 + kk];
                    acc[u][0] = ffma2(gv.x, cs0.x, acc[u][0]);
                    acc[u][0] = ffma2(gv.y, cs1.x, acc[u][0]);
                    acc[u][1] = ffma2(gv.x, cs0.y, acc[u][1]);
                    acc[u][1] = ffma2(gv.y, cs1.y, acc[u][1]);
                    if (w0 == 0) {
                        aN[u] += u2f(gv.x).x - u2f(gv.y).x;
                    }
                }
            }
            #pragma unroll
            for (int u = 0; u < 4; ++u) {
                const int h = hb + u * 4 + rl;
                float2 a0 = u2f(acc[u][0]);
                float2 a1 = u2f(acc[u][1]);
                float y00 = a0.x - a0.y + bias_o;
                float y01 = a1.x - a1.y + bias_o;
                float y10 = a0.x + a0.y + bias_o;
                float y11 = a1.x + a1.y + bias_o;
                *(float2*)&yp[h * 256 + w0] = make_float2(y00, y01);
                if (w0 == 0) {
                    yp[h * 256 + 255] = y11;
                    yp[h * 256 + 128] = aN[u] + bias_o;
                } else {
                    yp[h * 256 + (255 - w0)] = y11;
                    yp[h * 256 + (256 - w0)] = y10;
                }
            }
        }
        __syncthreads();
    }
}

// ---------------------------------------------------------------------------
extern "C" void kernel_launch(void* const* d_in, const int* in_sizes, int n_in,
                              void* d_out, int out_size) {
    const float* x    = (const float*)d_in[0];
    const float* wts  = (const float*)d_in[1];
    const float* bias = (const float*)d_in[2];
    float* out = (float*)d_out;

    cudaFuncSetAttribute(fwd_kernel, cudaFuncAttributeMaxDynamicSharedMemorySize,
                         FWD_SMEM_BYTES);
    cudaFuncSetAttribute(inv_kernel, cudaFuncAttributeMaxDynamicSharedMemorySize,
                         INV_SMEM_BYTES);

    fwd_kernel<<<Bn * CIN, 256, FWD_SMEM_BYTES>>>(x);
    mix_kernel<<<1024, 256>>>(wts);
    inv_kernel<<<Bn * COUT, 256, INV_SMEM_BYTES>>>(bias, out);
}

// round 9
// speedup vs baseline: 1.2172x; 1.2172x over previous
#include <cuda_runtime.h>
#include <math.h>

typedef unsigned long long u64;
typedef ulonglong2 u64x2;

#define Hn   256
#define Wn   256
#define CIN  64
#define COUT 64
#define Bn   16

__device__ __forceinline__ u64 f2u(float lo, float hi) {
    u64 r; asm("mov.b64 %0, {%1,%2};" : "=l"(r) : "f"(lo), "f"(hi)); return r;
}
__device__ __forceinline__ float2 u2f(u64 v) {
    float2 r; asm("mov.b64 {%0,%1}, %2;" : "=f"(r.x), "=f"(r.y) : "l"(v)); return r;
}
__device__ __forceinline__ u64 ffma2(u64 a, u64 b, u64 c) {
    u64 d; asm("fma.rn.f32x2 %0, %1, %2, %3;" : "=l"(d) : "l"(a), "l"(b), "l"(c));
    return d;
}

// Intermediate spectra, packed (re, im) in one u64
__device__ u64 g_X[Bn * CIN * 1024];
__device__ u64 g_S[Bn * COUT * 1024];

// ---------------------------------------------------------------------------
// Forward v4: R2 structure (32-row chunks, 2x2 tiles, 2 blocks/SM) with
// quarter-folded stage 1 (65 taps, kx-parity packing).
// smem: cs[65][32] f2 (c,-s) | t4[256] f4 (c,c,s,s) | xq[32][65] u64x2 |
//       x64[32] u64 | D[32][32] u64            total 62464 B
// ---------------------------------------------------------------------------
#define FWD_SMEM_BYTES (65*32*8 + 256*16 + 32*65*16 + 32*8 + 32*32*8)

__global__ __launch_bounds__(256, 2) void fwd_kernel(const float* __restrict__ x) {
    extern __shared__ char smraw[];
    float2* s_cs  = (float2*)smraw;                 // [w*32 + kx], w in [0,64]
    float4* s_t4  = (float4*)(s_cs + 65 * 32);      // [n] = (c, c, s, s)
    u64x2*  s_xq  = (u64x2*)(s_t4 + 256);           // [r*65 + w] = {(ee,om),(eo,op)}
    u64*    s_x64 = (u64*)(s_xq + 32 * 65);         // [r] = (xe64, xo64)
    u64*    s_D   = s_x64 + 32;                     // [r*32 + kx]

    const int t  = threadIdx.x;
    const int bi = blockIdx.x;
    const float* xp = x + (size_t)bi * (Hn * Wn);

    for (int idx = t; idx < 65 * 32; idx += 256) {
        int w = idx >> 5, kx = idx & 31;
        float sv, cv;
        sincospif(((w * kx) & 255) * (2.0f / 256.0f), &sv, &cv);
        s_cs[idx] = make_float2(cv, -sv);
    }
    {
        float sv, cv;
        sincospif(t * (2.0f / 256.0f), &sv, &cv);
        s_t4[t] = make_float4(cv, cv, sv, sv);
    }

    // warp tile: 8 rows x 16 kx ; thread tile 2 rows x 2 kx (kx0 even)
    const int warp = t >> 5, lane = t & 31;
    const int kxg  = warp & 1;
    const int rg   = warp >> 1;
    const int kl   = lane & 7;
    const int rl   = lane >> 3;
    const int kx0  = kxg * 16 + kl * 2;      // even
    const int row0 = rg * 8 + rl * 2;        // rows row0, row0+1 within chunk

    u64 X[2][2];   // stage-2 accumulators [ky off][kx off]
    X[0][0] = X[0][1] = X[1][0] = X[1][1] = 0ull;

    const u64* cs64 = (const u64*)s_cs;

    __syncthreads();

    for (int c = 0; c < 8; ++c) {
        const int h0 = c * 32;

        // ---- loader: quarter-fold 32 rows into s_xq / s_x64
        for (int idx = t; idx < 32 * 64; idx += 256) {
            int r = idx >> 6;
            int w = idx & 63;
            const float* row = xp + (size_t)(h0 + r) * Wn;
            u64x2 v;
            if (w == 0) {
                float x0 = row[0], x128 = row[128];
                v.x = f2u(x0 + x128, 0.f);
                v.y = f2u(x0 - x128, 0.f);
            } else {
                float xa = row[w],       xb = row[256 - w];
                float xc = row[128 - w], xd = row[128 + w];
                v.x = f2u(xa + xb + xc + xd, xa - xb - xc + xd);   // (ee, om)
                v.y = f2u(xa + xb - xc - xd, xa - xb + xc - xd);   // (eo, op)
            }
            s_xq[r * 65 + w] = v;
        }
        if (t < 32) {
            const float* row = xp + (size_t)(h0 + t) * Wn;
            float a = row[64], b = row[192];
            s_x64[t] = f2u(a + b, a - b);
        }
        __syncthreads();

        // ---- stage 1: quarter-folded row DFT (65 taps)
        {
            u64 a00 = 0ull, a01 = 0ull, a10 = 0ull, a11 = 0ull;
            #pragma unroll 4
            for (int w = 0; w < 64; ++w) {
                u64x2 tw = *(const u64x2*)&cs64[w * 32 + kx0];   // kx0 | kx0+1
                u64x2 v0 = s_xq[row0 * 65 + w];
                u64x2 v1 = s_xq[(row0 + 1) * 65 + w];
                a00 = ffma2(v0.x, tw.x, a00);    // even kx: (ee,om)*(c,-s)
                a01 = ffma2(v0.y, tw.y, a01);    // odd  kx: (eo,op)*(c,-s)
                a10 = ffma2(v1.x, tw.x, a10);
                a11 = ffma2(v1.y, tw.y, a11);
            }
            {   // tap w = 64: raw (xe64, xo64) for both parities
                u64x2 tw = *(const u64x2*)&cs64[64 * 32 + kx0];
                u64 v0 = s_x64[row0];
                u64 v1 = s_x64[row0 + 1];
                a00 = ffma2(v0, tw.x, a00);
                a01 = ffma2(v0, tw.y, a01);
                a10 = ffma2(v1, tw.x, a10);
                a11 = ffma2(v1, tw.y, a11);
            }
            u64x2 p0; p0.x = a00; p0.y = a01;
            u64x2 p1; p1.x = a10; p1.y = a11;
            *(u64x2*)&s_D[row0 * 32 + kx0]       = p0;
            *(u64x2*)&s_D[(row0 + 1) * 32 + kx0] = p1;
        }
        __syncthreads();

        // ---- stage 2: accumulate over h (unchanged from R2)
        #pragma unroll 4
        for (int r = 0; r < 32; ++r) {
            const int h = h0 + r;
            u64x2 dp = *(const u64x2*)&s_D[r * 32 + kx0];
            float2 d0 = u2f(dp.x), d1 = u2f(dp.y);
            u64 dq0 = f2u(d0.y, -d0.x);
            u64 dq1 = f2u(d1.y, -d1.x);
            u64x2 e0 = *(const u64x2*)&s_t4[(row0 * h) & 255];
            u64x2 e1 = *(const u64x2*)&s_t4[((row0 + 1) * h) & 255];
            X[0][0] = ffma2(dp.x, e0.x, X[0][0]);
            X[0][0] = ffma2(dq0,  e0.y, X[0][0]);
            X[0][1] = ffma2(dp.y, e0.x, X[0][1]);
            X[0][1] = ffma2(dq1,  e0.y, X[0][1]);
            X[1][0] = ffma2(dp.x, e1.x, X[1][0]);
            X[1][0] = ffma2(dq0,  e1.y, X[1][0]);
            X[1][1] = ffma2(dp.y, e1.x, X[1][1]);
            X[1][1] = ffma2(dq1,  e1.y, X[1][1]);
        }
        __syncthreads();
    }

    #pragma unroll
    for (int j = 0; j < 2; ++j)
        #pragma unroll
        for (int i = 0; i < 2; ++i)
            g_X[(size_t)bi * 1024 + (row0 + j) * 32 + kx0 + i] = X[j][i];
}

// ---------------------------------------------------------------------------
// Mix (unchanged)
// ---------------------------------------------------------------------------
__global__ __launch_bounds__(256) void mix_kernel(const float* __restrict__ wts) {
    __shared__ float s_W[CIN * COUT];
    __shared__ u64   s_X[Bn * CIN];
    const int t = threadIdx.x;
    const int m = blockIdx.x;

    for (int e = t; e < CIN * COUT; e += 256)
        s_W[e] = wts[(size_t)e * 1024 + m];
    for (int e = t; e < Bn * CIN; e += 256)
        s_X[e] = g_X[(size_t)e * 1024 + m];
    __syncthreads();

    const int o  = t & 63;
    const int bq = t >> 6;
    u64 acc[4] = {0ull, 0ull, 0ull, 0ull};

    #pragma unroll 8
    for (int i = 0; i < CIN; ++i) {
        float wv = s_W[i * 64 + o];
        u64 wp = f2u(wv, wv);
        #pragma unroll
        for (int j = 0; j < 4; ++j)
            acc[j] = ffma2(s_X[(bq * 4 + j) * 64 + i], wp, acc[j]);
    }
    #pragma unroll
    for (int j = 0; j < 4; ++j)
        g_S[((size_t)(bq * 4 + j) * 64 + o) * 1024 + m] = acc[j];
}

// ---------------------------------------------------------------------------
// Inverse (unchanged)
// ---------------------------------------------------------------------------
#define INV_SMEM_BYTES (32*130*8 + 256*16 + 32*32*8 + 16*32*8)

__global__ __launch_bounds__(256) void inv_kernel(const float* __restrict__ bias,
                                                  float* __restrict__ out) {
    extern __shared__ char smraw[];
    float2* s_ci  = (float2*)smraw;
    float4* s_t4i = (float4*)(s_ci + 32 * 130);
    u64*    s_S   = (u64*)(s_t4i + 256);
    u64*    s_G   = s_S + 32 * 32;

    const int t  = threadIdx.x;
    const int bo = blockIdx.x;
    const int o  = bo & 63;

    for (int idx = t; idx < 32 * 129; idx += 256) {
        int kk = idx / 129;
        int w  = idx - kk * 129;
        float sv, cv;
        sincospif(((kk * w) & 255) * (2.0f / 256.0f), &sv, &cv);
        s_ci[kk * 130 + w] = make_float2(cv, sv);
    }
    {
        float sv, cv;
        sincospif(t * (2.0f / 256.0f), &sv, &cv);
        s_t4i[t] = make_float4(cv, sv, -sv, cv);
    }
    for (int e = t; e < 1024; e += 256) {
        float2 v  = u2f(g_S[(size_t)bo * 1024 + e]);
        float sc  = ((e & 31) == 0 ? 1.f : 2.f) * (1.f / 65536.f);
        s_S[e] = f2u(v.x * sc, v.y * sc);
    }
    const float bias_o = bias[o];
    __syncthreads();

    const int kx = t & 31, r2 = t >> 5;
    const int warp = t >> 5, lane = t & 31;
    const int wl = lane & 7, rl = lane >> 3;
    const int w0 = warp * 16 + wl * 2;

    const u64* ci64 = (const u64*)s_ci;
    float* yp = out + (size_t)bo * (Hn * Wn);

    for (int c = 0; c < 16; ++c) {
        const int hb = c * 16;
        {
            const int h1 = hb + r2, h2 = h1 + 8;
            u64 a1 = 0ull, a2 = 0ull;
            #pragma unroll 8
            for (int ky = 0; ky < 32; ++ky) {
                float2 sv = u2f(s_S[ky * 32 + kx]);
                u64 sxx = f2u(sv.x, sv.x);
                u64 syy = f2u(sv.y, sv.y);
                u64x2 e1 = *(const u64x2*)&s_t4i[(ky * h1) & 255];
                u64x2 e2 = *(const u64x2*)&s_t4i[(ky * h2) & 255];
                a1 = ffma2(sxx, e1.x, a1);
                a1 = ffma2(syy, e1.y, a1);
                a2 = ffma2(sxx, e2.x, a2);
                a2 = ffma2(syy, e2.y, a2);
            }
            s_G[r2 * 32 + kx]       = a1;
            s_G[(r2 + 8) * 32 + kx] = a2;
        }
        __syncthreads();
        {
            u64 acc[4][2];
            float aN[4];
            #pragma unroll
            for (int u = 0; u < 4; ++u) {
                acc[u][0] = acc[u][1] = 0ull; aN[u] = 0.f;
            }
            #pragma unroll 4
            for (int kk = 0; kk < 32; kk += 2) {
                u64x2 cs0 = *(const u64x2*)&ci64[kk * 130 + w0];
                u64x2 cs1 = *(const u64x2*)&ci64[(kk + 1) * 130 + w0];
                #pragma unroll
                for (int u = 0; u < 4; ++u) {
                    u64x2 gv = *(const u64x2*)&s_G[(u * 4 + rl) * 32 + kk];
                    acc[u][0] = ffma2(gv.x, cs0.x, acc[u][0]);
                    acc[u][0] = ffma2(gv.y, cs1.x, acc[u][0]);
                    acc[u][1] = ffma2(gv.x, cs0.y, acc[u][1]);
                    acc[u][1] = ffma2(gv.y, cs1.y, acc[u][1]);
                    if (w0 == 0) {
                        aN[u] += u2f(gv.x).x - u2f(gv.y).x;
                    }
                }
            }
            #pragma unroll
            for (int u = 0; u < 4; ++u) {
                const int h = hb + u * 4 + rl;
                float2 a0 = u2f(acc[u][0]);
                float2 a1 = u2f(acc[u][1]);
                float y00 = a0.x - a0.y + bias_o;
                float y01 = a1.x - a1.y + bias_o;
                float y10 = a0.x + a0.y + bias_o;
                float y11 = a1.x + a1.y + bias_o;
                *(float2*)&yp[h * 256 + w0] = make_float2(y00, y01);
                if (w0 == 0) {
                    yp[h * 256 + 255] = y11;
                    yp[h * 256 + 128] = aN[u] + bias_o;
                } else {
                    yp[h * 256 + (255 - w0)] = y11;
                    yp[h * 256 + (256 - w0)] = y10;
                }
            }
        }
        __syncthreads();
    }
}

// ---------------------------------------------------------------------------
extern "C" void kernel_launch(void* const* d_in, const int* in_sizes, int n_in,
                              void* d_out, int out_size) {
    const float* x    = (const float*)d_in[0];
    const float* wts  = (const float*)d_in[1];
    const float* bias = (const float*)d_in[2];
    float* out = (float*)d_out;

    cudaFuncSetAttribute(fwd_kernel, cudaFuncAttributeMaxDynamicSharedMemorySize,
                         FWD_SMEM_BYTES);
    cudaFuncSetAttribute(inv_kernel, cudaFuncAttributeMaxDynamicSharedMemorySize,
                         INV_SMEM_BYTES);

    fwd_kernel<<<Bn * CIN, 256, FWD_SMEM_BYTES>>>(x);
    mix_kernel<<<1024, 256>>>(wts);
    inv_kernel<<<Bn * COUT, 256, INV_SMEM_BYTES>>>(bias, out);
}

// round 10
// speedup vs baseline: 1.3753x; 1.1299x over previous
#include <cuda_runtime.h>
#include <math.h>

typedef unsigned long long u64;
typedef ulonglong2 u64x2;

#define Hn   256
#define Wn   256
#define CIN  64
#define COUT 64
#define Bn   16

__device__ __forceinline__ u64 f2u(float lo, float hi) {
    u64 r; asm("mov.b64 %0, {%1,%2};" : "=l"(r) : "f"(lo), "f"(hi)); return r;
}
__device__ __forceinline__ float2 u2f(u64 v) {
    float2 r; asm("mov.b64 {%0,%1}, %2;" : "=f"(r.x), "=f"(r.y) : "l"(v)); return r;
}
__device__ __forceinline__ u64 ffma2(u64 a, u64 b, u64 c) {
    u64 d; asm("fma.rn.f32x2 %0, %1, %2, %3;" : "=l"(d) : "l"(a), "l"(b), "l"(c));
    return d;
}
__device__ __forceinline__ unsigned smem_u32(const void* p) {
    unsigned a;
    asm("{ .reg .u64 t; cvta.to.shared.u64 t, %1; cvt.u32.u64 %0, t; }"
        : "=r"(a) : "l"(p));
    return a;
}

// Intermediate spectra, packed (re, im) in one u64
__device__ u64 g_X[Bn * CIN * 1024];
__device__ u64 g_S[Bn * COUT * 1024];

// ---------------------------------------------------------------------------
// Forward v5: v4 + cp.async software pipeline for the raw input chunk.
// smem: cs[65][32] f2 | t4[256] f4 | raw[32][256] f32 | xq[32][65] u64x2 |
//       x64[32] u64 | D[32][32] u64        total 95232 B  (2 blocks/SM)
// ---------------------------------------------------------------------------
#define FWD_SMEM_BYTES (65*32*8 + 256*16 + 32*256*4 + 32*65*16 + 32*8 + 32*32*8)

__global__ __launch_bounds__(256, 2) void fwd_kernel(const float* __restrict__ x) {
    extern __shared__ char smraw[];
    float2* s_cs  = (float2*)smraw;                 // [w*32 + kx], w in [0,64]
    float4* s_t4  = (float4*)(s_cs + 65 * 32);      // [n] = (c, c, s, s)
    float*  s_raw = (float*)(s_t4 + 256);           // [r*256 + q] raw chunk
    u64x2*  s_xq  = (u64x2*)(s_raw + 32 * 256);     // [r*65 + w]
    u64*    s_x64 = (u64*)(s_xq + 32 * 65);         // [r]
    u64*    s_D   = s_x64 + 32;                     // [r*32 + kx]

    const int t  = threadIdx.x;
    const int bi = blockIdx.x;
    const float* xp = x + (size_t)bi * (Hn * Wn);

    // ---- issue cp.async for chunk 0 immediately (overlaps table build)
    const unsigned raw_base = smem_u32(s_raw);
    {
        #pragma unroll
        for (int j = 0; j < 8; ++j) {
            int e = t + j * 256;              // over 2048 float4
            const float* src = xp + e * 4;    // chunk 0: h0 = 0
            unsigned dst = raw_base + e * 16;
            asm volatile("cp.async.ca.shared.global [%0], [%1], 16;"
                         :: "r"(dst), "l"(src));
        }
        asm volatile("cp.async.commit_group;");
    }

    for (int idx = t; idx < 65 * 32; idx += 256) {
        int w = idx >> 5, kx = idx & 31;
        float sv, cv;
        sincospif(((w * kx) & 255) * (2.0f / 256.0f), &sv, &cv);
        s_cs[idx] = make_float2(cv, -sv);
    }
    {
        float sv, cv;
        sincospif(t * (2.0f / 256.0f), &sv, &cv);
        s_t4[t] = make_float4(cv, cv, sv, sv);
    }

    // warp tile: 8 rows x 16 kx ; thread tile 2 rows x 2 kx (kx0 even)
    const int warp = t >> 5, lane = t & 31;
    const int kxg  = warp & 1;
    const int rg   = warp >> 1;
    const int kl   = lane & 7;
    const int rl   = lane >> 3;
    const int kx0  = kxg * 16 + kl * 2;      // even
    const int row0 = rg * 8 + rl * 2;        // rows row0, row0+1 within chunk

    u64 X[2][2];
    X[0][0] = X[0][1] = X[1][0] = X[1][1] = 0ull;

    const u64* cs64 = (const u64*)s_cs;

    asm volatile("cp.async.wait_group 0;");
    __syncthreads();

    for (int c = 0; c < 8; ++c) {
        // ---- fold raw (smem) -> xq / x64
        #pragma unroll 2
        for (int idx = t; idx < 32 * 64; idx += 256) {
            int r = idx >> 6;
            int w = idx & 63;
            const float* row = s_raw + r * 256;
            u64x2 v;
            if (w == 0) {
                float x0 = row[0], x128 = row[128];
                v.x = f2u(x0 + x128, 0.f);
                v.y = f2u(x0 - x128, 0.f);
            } else {
                float xa = row[w],       xb = row[256 - w];
                float xc = row[128 - w], xd = row[128 + w];
                v.x = f2u(xa + xb + xc + xd, xa - xb - xc + xd);   // (ee, om)
                v.y = f2u(xa + xb - xc - xd, xa - xb + xc - xd);   // (eo, op)
            }
            s_xq[r * 65 + w] = v;
        }
        if (t < 32) {
            const float* row = s_raw + t * 256;
            float a = row[64], b = row[192];
            s_x64[t] = f2u(a + b, a - b);
        }
        __syncthreads();   // fold done; s_raw free for the next chunk

        // ---- prefetch next chunk raw (overlaps stage 1 + stage 2)
        if (c < 7) {
            const float* xc = xp + (size_t)(c + 1) * 32 * Wn;
            #pragma unroll
            for (int j = 0; j < 8; ++j) {
                int e = t + j * 256;
                const float* src = xc + e * 4;
                unsigned dst = raw_base + e * 16;
                asm volatile("cp.async.ca.shared.global [%0], [%1], 16;"
                             :: "r"(dst), "l"(src));
            }
            asm volatile("cp.async.commit_group;");
        }

        // ---- stage 1: quarter-folded row DFT (65 taps)
        {
            u64 a00 = 0ull, a01 = 0ull, a10 = 0ull, a11 = 0ull;
            #pragma unroll 4
            for (int w = 0; w < 64; ++w) {
                u64x2 tw = *(const u64x2*)&cs64[w * 32 + kx0];
                u64x2 v0 = s_xq[row0 * 65 + w];
                u64x2 v1 = s_xq[(row0 + 1) * 65 + w];
                a00 = ffma2(v0.x, tw.x, a00);
                a01 = ffma2(v0.y, tw.y, a01);
                a10 = ffma2(v1.x, tw.x, a10);
                a11 = ffma2(v1.y, tw.y, a11);
            }
            {   // tap w = 64
                u64x2 tw = *(const u64x2*)&cs64[64 * 32 + kx0];
                u64 v0 = s_x64[row0];
                u64 v1 = s_x64[row0 + 1];
                a00 = ffma2(v0, tw.x, a00);
                a01 = ffma2(v0, tw.y, a01);
                a10 = ffma2(v1, tw.x, a10);
                a11 = ffma2(v1, tw.y, a11);
            }
            u64x2 p0; p0.x = a00; p0.y = a01;
            u64x2 p1; p1.x = a10; p1.y = a11;
            *(u64x2*)&s_D[row0 * 32 + kx0]       = p0;
            *(u64x2*)&s_D[(row0 + 1) * 32 + kx0] = p1;
        }
        __syncthreads();

        // ---- stage 2: accumulate over h
        const int h0 = c * 32;
        #pragma unroll 4
        for (int r = 0; r < 32; ++r) {
            const int h = h0 + r;
            u64x2 dp = *(const u64x2*)&s_D[r * 32 + kx0];
            float2 d0 = u2f(dp.x), d1 = u2f(dp.y);
            u64 dq0 = f2u(d0.y, -d0.x);
            u64 dq1 = f2u(d1.y, -d1.x);
            u64x2 e0 = *(const u64x2*)&s_t4[(row0 * h) & 255];
            u64x2 e1 = *(const u64x2*)&s_t4[((row0 + 1) * h) & 255];
            X[0][0] = ffma2(dp.x, e0.x, X[0][0]);
            X[0][0] = ffma2(dq0,  e0.y, X[0][0]);
            X[0][1] = ffma2(dp.y, e0.x, X[0][1]);
            X[0][1] = ffma2(dq1,  e0.y, X[0][1]);
            X[1][0] = ffma2(dp.x, e1.x, X[1][0]);
            X[1][0] = ffma2(dq0,  e1.y, X[1][0]);
            X[1][1] = ffma2(dp.y, e1.x, X[1][1]);
            X[1][1] = ffma2(dq1,  e1.y, X[1][1]);
        }
        if (c < 7) asm volatile("cp.async.wait_group 0;");
        __syncthreads();
    }

    #pragma unroll
    for (int j = 0; j < 2; ++j)
        #pragma unroll
        for (int i = 0; i < 2; ++i)
            g_X[(size_t)bi * 1024 + (row0 + j) * 32 + kx0 + i] = X[j][i];
}

// ---------------------------------------------------------------------------
// Mix (unchanged)
// ---------------------------------------------------------------------------
__global__ __launch_bounds__(256) void mix_kernel(const float* __restrict__ wts) {
    __shared__ float s_W[CIN * COUT];
    __shared__ u64   s_X[Bn * CIN];
    const int t = threadIdx.x;
    const int m = blockIdx.x;

    for (int e = t; e < CIN * COUT; e += 256)
        s_W[e] = wts[(size_t)e * 1024 + m];
    for (int e = t; e < Bn * CIN; e += 256)
        s_X[e] = g_X[(size_t)e * 1024 + m];
    __syncthreads();

    const int o  = t & 63;
    const int bq = t >> 6;
    u64 acc[4] = {0ull, 0ull, 0ull, 0ull};

    #pragma unroll 8
    for (int i = 0; i < CIN; ++i) {
        float wv = s_W[i * 64 + o];
        u64 wp = f2u(wv, wv);
        #pragma unroll
        for (int j = 0; j < 4; ++j)
            acc[j] = ffma2(s_X[(bq * 4 + j) * 64 + i], wp, acc[j]);
    }
    #pragma unroll
    for (int j = 0; j < 4; ++j)
        g_S[((size_t)(bq * 4 + j) * 64 + o) * 1024 + m] = acc[j];
}

// ---------------------------------------------------------------------------
// Inverse (unchanged)
// ---------------------------------------------------------------------------
#define INV_SMEM_BYTES (32*130*8 + 256*16 + 32*32*8 + 16*32*8)

__global__ __launch_bounds__(256) void inv_kernel(const float* __restrict__ bias,
                                                  float* __restrict__ out) {
    extern __shared__ char smraw[];
    float2* s_ci  = (float2*)smraw;
    float4* s_t4i = (float4*)(s_ci + 32 * 130);
    u64*    s_S   = (u64*)(s_t4i + 256);
    u64*    s_G   = s_S + 32 * 32;

    const int t  = threadIdx.x;
    const int bo = blockIdx.x;
    const int o  = bo & 63;

    for (int idx = t; idx < 32 * 129; idx += 256) {
        int kk = idx / 129;
        int w  = idx - kk * 129;
        float sv, cv;
        sincospif(((kk * w) & 255) * (2.0f / 256.0f), &sv, &cv);
        s_ci[kk * 130 + w] = make_float2(cv, sv);
    }
    {
        float sv, cv;
        sincospif(t * (2.0f / 256.0f), &sv, &cv);
        s_t4i[t] = make_float4(cv, sv, -sv, cv);
    }
    for (int e = t; e < 1024; e += 256) {
        float2 v  = u2f(g_S[(size_t)bo * 1024 + e]);
        float sc  = ((e & 31) == 0 ? 1.f : 2.f) * (1.f / 65536.f);
        s_S[e] = f2u(v.x * sc, v.y * sc);
    }
    const float bias_o = bias[o];
    __syncthreads();

    const int kx = t & 31, r2 = t >> 5;
    const int warp = t >> 5, lane = t & 31;
    const int wl = lane & 7, rl = lane >> 3;
    const int w0 = warp * 16 + wl * 2;

    const u64* ci64 = (const u64*)s_ci;
    float* yp = out + (size_t)bo * (Hn * Wn);

    for (int c = 0; c < 16; ++c) {
        const int hb = c * 16;
        {
            const int h1 = hb + r2, h2 = h1 + 8;
            u64 a1 = 0ull, a2 = 0ull;
            #pragma unroll 8
            for (int ky = 0; ky < 32; ++ky) {
                float2 sv = u2f(s_S[ky * 32 + kx]);
                u64 sxx = f2u(sv.x, sv.x);
                u64 syy = f2u(sv.y, sv.y);
                u64x2 e1 = *(const u64x2*)&s_t4i[(ky * h1) & 255];
                u64x2 e2 = *(const u64x2*)&s_t4i[(ky * h2) & 255];
                a1 = ffma2(sxx, e1.x, a1);
                a1 = ffma2(syy, e1.y, a1);
                a2 = ffma2(sxx, e2.x, a2);
                a2 = ffma2(syy, e2.y, a2);
            }
            s_G[r2 * 32 + kx]       = a1;
            s_G[(r2 + 8) * 32 + kx] = a2;
        }
        __syncthreads();
        {
            u64 acc[4][2];
            float aN[4];
            #pragma unroll
            for (int u = 0; u < 4; ++u) {
                acc[u][0] = acc[u][1] = 0ull; aN[u] = 0.f;
            }
            #pragma unroll 4
            for (int kk = 0; kk < 32; kk += 2) {
                u64x2 cs0 = *(const u64x2*)&ci64[kk * 130 + w0];
                u64x2 cs1 = *(const u64x2*)&ci64[(kk + 1) * 130 + w0];
                #pragma unroll
                for (int u = 0; u < 4; ++u) {
                    u64x2 gv = *(const u64x2*)&s_G[(u * 4 + rl) * 32 + kk];
                    acc[u][0] = ffma2(gv.x, cs0.x, acc[u][0]);
                    acc[u][0] = ffma2(gv.y, cs1.x, acc[u][0]);
                    acc[u][1] = ffma2(gv.x, cs0.y, acc[u][1]);
                    acc[u][1] = ffma2(gv.y, cs1.y, acc[u][1]);
                    if (w0 == 0) {
                        aN[u] += u2f(gv.x).x - u2f(gv.y).x;
                    }
                }
            }
            #pragma unroll
            for (int u = 0; u < 4; ++u) {
                const int h = hb + u * 4 + rl;
                float2 a0 = u2f(acc[u][0]);
                float2 a1 = u2f(acc[u][1]);
                float y00 = a0.x - a0.y + bias_o;
                float y01 = a1.x - a1.y + bias_o;
                float y10 = a0.x + a0.y + bias_o;
                float y11 = a1.x + a1.y + bias_o;
                *(float2*)&yp[h * 256 + w0] = make_float2(y00, y01);
                if (w0 == 0) {
                    yp[h * 256 + 255] = y11;
                    yp[h * 256 + 128] = aN[u] + bias_o;
                } else {
                    yp[h * 256 + (255 - w0)] = y11;
                    yp[h * 256 + (256 - w0)] = y10;
                }
            }
        }
        __syncthreads();
    }
}

// ---------------------------------------------------------------------------
extern "C" void kernel_launch(void* const* d_in, const int* in_sizes, int n_in,
                              void* d_out, int out_size) {
    const float* x    = (const float*)d_in[0];
    const float* wts  = (const float*)d_in[1];
    const float* bias = (const float*)d_in[2];
    float* out = (float*)d_out;

    cudaFuncSetAttribute(fwd_kernel, cudaFuncAttributeMaxDynamicSharedMemorySize,
                         FWD_SMEM_BYTES);
    cudaFuncSetAttribute(inv_kernel, cudaFuncAttributeMaxDynamicSharedMemorySize,
                         INV_SMEM_BYTES);

    fwd_kernel<<<Bn * CIN, 256, FWD_SMEM_BYTES>>>(x);
    mix_kernel<<<1024, 256>>>(wts);
    inv_kernel<<<Bn * COUT, 256, INV_SMEM_BYTES>>>(bias, out);
}

// round 11
// speedup vs baseline: 1.4999x; 1.0906x over previous
#include <cuda_runtime.h>
#include <math.h>

typedef unsigned long long u64;
typedef ulonglong2 u64x2;

#define Hn   256
#define Wn   256
#define CIN  64
#define COUT 64
#define Bn   16

__device__ __forceinline__ u64 f2u(float lo, float hi) {
    u64 r; asm("mov.b64 %0, {%1,%2};" : "=l"(r) : "f"(lo), "f"(hi)); return r;
}
__device__ __forceinline__ float2 u2f(u64 v) {
    float2 r; asm("mov.b64 {%0,%1}, %2;" : "=f"(r.x), "=f"(r.y) : "l"(v)); return r;
}
__device__ __forceinline__ u64 ffma2(u64 a, u64 b, u64 c) {
    u64 d; asm("fma.rn.f32x2 %0, %1, %2, %3;" : "=l"(d) : "l"(a), "l"(b), "l"(c));
    return d;
}
__device__ __forceinline__ u64 fadd2(u64 a, u64 b) {
    u64 d; asm("add.rn.f32x2 %0, %1, %2;" : "=l"(d) : "l"(a), "l"(b));
    return d;
}
__device__ __forceinline__ u64 fsub2(u64 a, u64 b) {
    return fadd2(a, b ^ 0x8000000080000000ull);
}
__device__ __forceinline__ unsigned smem_u32(const void* p) {
    unsigned a;
    asm("{ .reg .u64 t; cvta.to.shared.u64 t, %1; cvt.u32.u64 %0, t; }"
        : "=r"(a) : "l"(p));
    return a;
}

// Intermediate spectra, packed (re, im) in one u64
__device__ u64 g_X[Bn * CIN * 1024];
__device__ u64 g_S[Bn * COUT * 1024];

// ---------------------------------------------------------------------------
// Forward v5 (unchanged from R9): quarter-fold + cp.async pipeline
// ---------------------------------------------------------------------------
#define FWD_SMEM_BYTES (65*32*8 + 256*16 + 32*256*4 + 32*65*16 + 32*8 + 32*32*8)

__global__ __launch_bounds__(256, 2) void fwd_kernel(const float* __restrict__ x) {
    extern __shared__ char smraw[];
    float2* s_cs  = (float2*)smraw;
    float4* s_t4  = (float4*)(s_cs + 65 * 32);
    float*  s_raw = (float*)(s_t4 + 256);
    u64x2*  s_xq  = (u64x2*)(s_raw + 32 * 256);
    u64*    s_x64 = (u64*)(s_xq + 32 * 65);
    u64*    s_D   = s_x64 + 32;

    const int t  = threadIdx.x;
    const int bi = blockIdx.x;
    const float* xp = x + (size_t)bi * (Hn * Wn);

    const unsigned raw_base = smem_u32(s_raw);
    {
        #pragma unroll
        for (int j = 0; j < 8; ++j) {
            int e = t + j * 256;
            const float* src = xp + e * 4;
            unsigned dst = raw_base + e * 16;
            asm volatile("cp.async.ca.shared.global [%0], [%1], 16;"
                         :: "r"(dst), "l"(src));
        }
        asm volatile("cp.async.commit_group;");
    }

    for (int idx = t; idx < 65 * 32; idx += 256) {
        int w = idx >> 5, kx = idx & 31;
        float sv, cv;
        sincospif(((w * kx) & 255) * (2.0f / 256.0f), &sv, &cv);
        s_cs[idx] = make_float2(cv, -sv);
    }
    {
        float sv, cv;
        sincospif(t * (2.0f / 256.0f), &sv, &cv);
        s_t4[t] = make_float4(cv, cv, sv, sv);
    }

    const int warp = t >> 5, lane = t & 31;
    const int kxg  = warp & 1;
    const int rg   = warp >> 1;
    const int kl   = lane & 7;
    const int rl   = lane >> 3;
    const int kx0  = kxg * 16 + kl * 2;
    const int row0 = rg * 8 + rl * 2;

    u64 X[2][2];
    X[0][0] = X[0][1] = X[1][0] = X[1][1] = 0ull;

    const u64* cs64 = (const u64*)s_cs;

    asm volatile("cp.async.wait_group 0;");
    __syncthreads();

    for (int c = 0; c < 8; ++c) {
        #pragma unroll 2
        for (int idx = t; idx < 32 * 64; idx += 256) {
            int r = idx >> 6;
            int w = idx & 63;
            const float* row = s_raw + r * 256;
            u64x2 v;
            if (w == 0) {
                float x0 = row[0], x128 = row[128];
                v.x = f2u(x0 + x128, 0.f);
                v.y = f2u(x0 - x128, 0.f);
            } else {
                float xa = row[w],       xb = row[256 - w];
                float xc = row[128 - w], xd = row[128 + w];
                v.x = f2u(xa + xb + xc + xd, xa - xb - xc + xd);
                v.y = f2u(xa + xb - xc - xd, xa - xb + xc - xd);
            }
            s_xq[r * 65 + w] = v;
        }
        if (t < 32) {
            const float* row = s_raw + t * 256;
            float a = row[64], b = row[192];
            s_x64[t] = f2u(a + b, a - b);
        }
        __syncthreads();

        if (c < 7) {
            const float* xc = xp + (size_t)(c + 1) * 32 * Wn;
            #pragma unroll
            for (int j = 0; j < 8; ++j) {
                int e = t + j * 256;
                const float* src = xc + e * 4;
                unsigned dst = raw_base + e * 16;
                asm volatile("cp.async.ca.shared.global [%0], [%1], 16;"
                             :: "r"(dst), "l"(src));
            }
            asm volatile("cp.async.commit_group;");
        }

        {
            u64 a00 = 0ull, a01 = 0ull, a10 = 0ull, a11 = 0ull;
            #pragma unroll 4
            for (int w = 0; w < 64; ++w) {
                u64x2 tw = *(const u64x2*)&cs64[w * 32 + kx0];
                u64x2 v0 = s_xq[row0 * 65 + w];
                u64x2 v1 = s_xq[(row0 + 1) * 65 + w];
                a00 = ffma2(v0.x, tw.x, a00);
                a01 = ffma2(v0.y, tw.y, a01);
                a10 = ffma2(v1.x, tw.x, a10);
                a11 = ffma2(v1.y, tw.y, a11);
            }
            {
                u64x2 tw = *(const u64x2*)&cs64[64 * 32 + kx0];
                u64 v0 = s_x64[row0];
                u64 v1 = s_x64[row0 + 1];
                a00 = ffma2(v0, tw.x, a00);
                a01 = ffma2(v0, tw.y, a01);
                a10 = ffma2(v1, tw.x, a10);
                a11 = ffma2(v1, tw.y, a11);
            }
            u64x2 p0; p0.x = a00; p0.y = a01;
            u64x2 p1; p1.x = a10; p1.y = a11;
            *(u64x2*)&s_D[row0 * 32 + kx0]       = p0;
            *(u64x2*)&s_D[(row0 + 1) * 32 + kx0] = p1;
        }
        __syncthreads();

        const int h0 = c * 32;
        #pragma unroll 4
        for (int r = 0; r < 32; ++r) {
            const int h = h0 + r;
            u64x2 dp = *(const u64x2*)&s_D[r * 32 + kx0];
            float2 d0 = u2f(dp.x), d1 = u2f(dp.y);
            u64 dq0 = f2u(d0.y, -d0.x);
            u64 dq1 = f2u(d1.y, -d1.x);
            u64x2 e0 = *(const u64x2*)&s_t4[(row0 * h) & 255];
            u64x2 e1 = *(const u64x2*)&s_t4[((row0 + 1) * h) & 255];
            X[0][0] = ffma2(dp.x, e0.x, X[0][0]);
            X[0][0] = ffma2(dq0,  e0.y, X[0][0]);
            X[0][1] = ffma2(dp.y, e0.x, X[0][1]);
            X[0][1] = ffma2(dq1,  e0.y, X[0][1]);
            X[1][0] = ffma2(dp.x, e1.x, X[1][0]);
            X[1][0] = ffma2(dq0,  e1.y, X[1][0]);
            X[1][1] = ffma2(dp.y, e1.x, X[1][1]);
            X[1][1] = ffma2(dq1,  e1.y, X[1][1]);
        }
        if (c < 7) asm volatile("cp.async.wait_group 0;");
        __syncthreads();
    }

    #pragma unroll
    for (int j = 0; j < 2; ++j)
        #pragma unroll
        for (int i = 0; i < 2; ++i)
            g_X[(size_t)bi * 1024 + (row0 + j) * 32 + kx0 + i] = X[j][i];
}

// ---------------------------------------------------------------------------
// Mix (unchanged)
// ---------------------------------------------------------------------------
__global__ __launch_bounds__(256) void mix_kernel(const float* __restrict__ wts) {
    __shared__ float s_W[CIN * COUT];
    __shared__ u64   s_X[Bn * CIN];
    const int t = threadIdx.x;
    const int m = blockIdx.x;

    for (int e = t; e < CIN * COUT; e += 256)
        s_W[e] = wts[(size_t)e * 1024 + m];
    for (int e = t; e < Bn * CIN; e += 256)
        s_X[e] = g_X[(size_t)e * 1024 + m];
    __syncthreads();

    const int o  = t & 63;
    const int bq = t >> 6;
    u64 acc[4] = {0ull, 0ull, 0ull, 0ull};

    #pragma unroll 8
    for (int i = 0; i < CIN; ++i) {
        float wv = s_W[i * 64 + o];
        u64 wp = f2u(wv, wv);
        #pragma unroll
        for (int j = 0; j < 4; ++j)
            acc[j] = ffma2(s_X[(bq * 4 + j) * 64 + i], wp, acc[j]);
    }
    #pragma unroll
    for (int j = 0; j < 4; ++j)
        g_S[((size_t)(bq * 4 + j) * 64 + o) * 1024 + m] = acc[j];
}

// ---------------------------------------------------------------------------
// Inverse v2: kk-parity folded C2 (one 32-tap pass -> 4 output columns),
// row-packed G from C1, pre-duplicated twiddle table, 4 blocks/SM.
// smem: tw[32][65] u64x2 {(c,c),(s,s)} | t4i[256] f4 | S[1024] u64 |
//       G2[32][9] u64x2 {(gRh,gRh8),(gIh,gIh8)}      total 50176 B
// ---------------------------------------------------------------------------
#define INV_SMEM_BYTES (32*65*16 + 256*16 + 1024*8 + 32*9*16)

__global__ __launch_bounds__(256) void inv_kernel(const float* __restrict__ bias,
                                                  float* __restrict__ out) {
    extern __shared__ char smraw[];
    u64x2*  s_tw  = (u64x2*)smraw;                  // [kk*65 + w]
    float4* s_t4i = (float4*)(s_tw + 32 * 65);      // [n] = (c, s, -s, c)
    u64*    s_S   = (u64*)(s_t4i + 256);            // [ky*32 + kx], pre-scaled
    u64x2*  s_G2  = (u64x2*)(s_S + 1024);           // [kk*9 + rp]

    const int t  = threadIdx.x;
    const int bo = blockIdx.x;
    const int o  = bo & 63;

    for (int idx = t; idx < 32 * 65; idx += 256) {
        int kk = idx / 65;
        int w  = idx - kk * 65;
        float sv, cv;
        sincospif(((kk * w) & 255) * (2.0f / 256.0f), &sv, &cv);
        u64x2 e; e.x = f2u(cv, cv); e.y = f2u(sv, sv);
        s_tw[idx] = e;
    }
    {
        float sv, cv;
        sincospif(t * (2.0f / 256.0f), &sv, &cv);
        s_t4i[t] = make_float4(cv, sv, -sv, cv);
    }
    for (int e = t; e < 1024; e += 256) {
        float2 v  = u2f(g_S[(size_t)bo * 1024 + e]);
        float sc  = ((e & 31) == 0 ? 1.f : 2.f) * (1.f / 65536.f);
        s_S[e] = f2u(v.x * sc, v.y * sc);
    }
    const float bias_o = bias[o];
    const u64 b2 = f2u(bias_o, bias_o);
    __syncthreads();

    // C1 mapping: lane = kx, warp = r2 (row pair r2, r2+8)
    const int kx = t & 31, r2 = t >> 5;
    // C2 mapping: w = t&63 (cols w,128-w,128+w,256-w), rpg = t>>6 (rp, rp+4)
    const int w   = t & 63;
    const int rpg = t >> 6;
    const int rp0 = rpg, rp1 = rpg + 4;

    float* yp = out + (size_t)bo * (Hn * Wn);

    for (int c = 0; c < 16; ++c) {
        const int hb = c * 16;

        // ---- C1: G[h,kx] = sum_ky S * e^{+i 2pi ky h/256}, rows h1=hb+r2, h2=h1+8
        {
            const int h1 = hb + r2, h2 = h1 + 8;
            u64 a1 = 0ull, a2 = 0ull;
            #pragma unroll 8
            for (int ky = 0; ky < 32; ++ky) {
                float2 sv = u2f(s_S[ky * 32 + kx]);
                u64 sxx = f2u(sv.x, sv.x);
                u64 syy = f2u(sv.y, sv.y);
                u64x2 e1 = *(const u64x2*)&s_t4i[(ky * h1) & 255];
                u64x2 e2 = *(const u64x2*)&s_t4i[(ky * h2) & 255];
                a1 = ffma2(sxx, e1.x, a1);
                a1 = ffma2(syy, e1.y, a1);
                a2 = ffma2(sxx, e2.x, a2);
                a2 = ffma2(syy, e2.y, a2);
            }
            float2 A1 = u2f(a1), A2 = u2f(a2);
            u64x2 g; g.x = f2u(A1.x, A2.x); g.y = f2u(A1.y, A2.y);
            s_G2[kx * 9 + r2] = g;
        }
        __syncthreads();

        // ---- C2: parity-folded synthesis; 32 taps -> 4 cols x 4 rows
        {
            u64 Ce0 = 0ull, Se0 = 0ull, Co0 = 0ull, So0 = 0ull;
            u64 Ce1 = 0ull, Se1 = 0ull, Co1 = 0ull, So1 = 0ull;
            #pragma unroll 8
            for (int kk = 0; kk < 32; kk += 2) {
                u64x2 twE = s_tw[kk * 65 + w];
                u64x2 twO = s_tw[(kk + 1) * 65 + w];
                u64x2 gE0 = s_G2[kk * 9 + rp0];
                u64x2 gO0 = s_G2[(kk + 1) * 9 + rp0];
                u64x2 gE1 = s_G2[kk * 9 + rp1];
                u64x2 gO1 = s_G2[(kk + 1) * 9 + rp1];
                Ce0 = ffma2(gE0.x, twE.x, Ce0);
                Se0 = ffma2(gE0.y, twE.y, Se0);
                Co0 = ffma2(gO0.x, twO.x, Co0);
                So0 = ffma2(gO0.y, twO.y, So0);
                Ce1 = ffma2(gE1.x, twE.x, Ce1);
                Se1 = ffma2(gE1.y, twE.y, Se1);
                Co1 = ffma2(gO1.x, twO.x, Co1);
                So1 = ffma2(gO1.y, twO.y, So1);
            }
            #pragma unroll
            for (int p = 0; p < 2; ++p) {
                u64 Ce = p ? Ce1 : Ce0, Co = p ? Co1 : Co0;
                u64 Se = p ? Se1 : Se0, So = p ? So1 : So0;
                const int rp = p ? rp1 : rp0;
                const int hA = hb + rp, hB = hA + 8;
                u64 P = fadd2(Ce, Co), Q = fadd2(Se, So);
                u64 R = fsub2(Ce, Co), T = fsub2(Se, So);
                float2 yw  = u2f(fadd2(fsub2(P, Q), b2));   // col w
                float2 ymw = u2f(fadd2(fadd2(P, Q), b2));   // col 256-w
                float2 yr  = u2f(fadd2(fadd2(R, T), b2));   // col 128-w
                float2 yrw = u2f(fadd2(fsub2(R, T), b2));   // col 128+w
                yp[hA * 256 + w] = yw.x;
                yp[hB * 256 + w] = yw.y;
                yp[hA * 256 + ((256 - w) & 255)] = ymw.x;
                yp[hB * 256 + ((256 - w) & 255)] = ymw.y;
                yp[hA * 256 + (128 - w)] = yr.x;
                yp[hB * 256 + (128 - w)] = yr.y;
                yp[hA * 256 + (128 + w)] = yrw.x;
                yp[hB * 256 + (128 + w)] = yrw.y;
            }

            // cols 64 / 192: y64 = A - B, y192 = A + B
            // A = sum_m (-1)^m GR2[2m], B = sum_m (-1)^m GI2[2m+1]
            if (w == 0) {
                u64 A0 = 0ull, B0 = 0ull, A1v = 0ull, B1v = 0ull;
                #pragma unroll
                for (int m = 0; m < 16; m += 2) {
                    A0 = fadd2(A0, s_G2[(2 * m) * 9 + rp0].x);
                    B0 = fadd2(B0, s_G2[(2 * m + 1) * 9 + rp0].y);
                    A0 = fsub2(A0, s_G2[(2 * m + 2) * 9 + rp0].x);
                    B0 = fsub2(B0, s_G2[(2 * m + 3) * 9 + rp0].y);
                    A1v = fadd2(A1v, s_G2[(2 * m) * 9 + rp1].x);
                    B1v = fadd2(B1v, s_G2[(2 * m + 1) * 9 + rp1].y);
                    A1v = fsub2(A1v, s_G2[(2 * m + 2) * 9 + rp1].x);
                    B1v = fsub2(B1v, s_G2[(2 * m + 3) * 9 + rp1].y);
                }
                #pragma unroll
                for (int p = 0; p < 2; ++p) {
                    u64 A = p ? A1v : A0, Bv = p ? B1v : B0;
                    const int rp = p ? rp1 : rp0;
                    const int hA = hb + rp, hB = hA + 8;
                    float2 y64  = u2f(fadd2(fsub2(A, Bv), b2));
                    float2 y192 = u2f(fadd2(fadd2(A, Bv), b2));
                    yp[hA * 256 + 64]  = y64.x;
                    yp[hB * 256 + 64]  = y64.y;
                    yp[hA * 256 + 192] = y192.x;
                    yp[hB * 256 + 192] = y192.y;
                }
            }
        }
        __syncthreads();
    }
}

// ---------------------------------------------------------------------------
extern "C" void kernel_launch(void* const* d_in, const int* in_sizes, int n_in,
                              void* d_out, int out_size) {
    const float* x    = (const float*)d_in[0];
    const float* wts  = (const float*)d_in[1];
    const float* bias = (const float*)d_in[2];
    float* out = (float*)d_out;

    cudaFuncSetAttribute(fwd_kernel, cudaFuncAttributeMaxDynamicSharedMemorySize,
                         FWD_SMEM_BYTES);
    cudaFuncSetAttribute(inv_kernel, cudaFuncAttributeMaxDynamicSharedMemorySize,
                         INV_SMEM_BYTES);

    fwd_kernel<<<Bn * CIN, 256, FWD_SMEM_BYTES>>>(x);
    mix_kernel<<<1024, 256>>>(wts);
    inv_kernel<<<Bn * COUT, 256, INV_SMEM_BYTES>>>(bias, out);
}

// round 12
// speedup vs baseline: 1.6223x; 1.0816x over previous
#include <cuda_runtime.h>
#include <math.h>

typedef unsigned long long u64;
typedef ulonglong2 u64x2;

#define Hn   256
#define Wn   256
#define CIN  64
#define COUT 64
#define Bn   16

__device__ __forceinline__ u64 f2u(float lo, float hi) {
    u64 r; asm("mov.b64 %0, {%1,%2};" : "=l"(r) : "f"(lo), "f"(hi)); return r;
}
__device__ __forceinline__ float2 u2f(u64 v) {
    float2 r; asm("mov.b64 {%0,%1}, %2;" : "=f"(r.x), "=f"(r.y) : "l"(v)); return r;
}
__device__ __forceinline__ u64 ffma2(u64 a, u64 b, u64 c) {
    u64 d; asm("fma.rn.f32x2 %0, %1, %2, %3;" : "=l"(d) : "l"(a), "l"(b), "l"(c));
    return d;
}
__device__ __forceinline__ u64 fadd2(u64 a, u64 b) {
    u64 d; asm("add.rn.f32x2 %0, %1, %2;" : "=l"(d) : "l"(a), "l"(b));
    return d;
}
__device__ __forceinline__ u64 fsub2(u64 a, u64 b) {
    return fadd2(a, b ^ 0x8000000080000000ull);
}
__device__ __forceinline__ unsigned smem_u32(const void* p) {
    unsigned a;
    asm("{ .reg .u64 t; cvta.to.shared.u64 t, %1; cvt.u32.u64 %0, t; }"
        : "=r"(a) : "l"(p));
    return a;
}

// Intermediate spectra, packed (re, im) in one u64
__device__ u64 g_X[Bn * CIN * 1024];
__device__ u64 g_S[Bn * COUT * 1024];

// ---------------------------------------------------------------------------
// Forward v6: quarter-fold stage1 + cp.async pipeline + h±128-folded stage2.
// Chunk order 0,4,1,5,2,6,3,7; stage2 runs on pairs (c, c+4).
// smem: cs[65][32] f2 | t4[256] f4 | raw[32][256] f32 | xq[32][65] u64x2 |
//       x64[32] u64 | D_A[32][32] u64 | D_B[32][32] u64     total 103424 B
// ---------------------------------------------------------------------------
#define FWD_SMEM_BYTES (65*32*8 + 256*16 + 32*256*4 + 32*65*16 + 32*8 + 2*32*32*8)

__global__ __launch_bounds__(256, 2) void fwd_kernel(const float* __restrict__ x) {
    extern __shared__ char smraw[];
    float2* s_cs  = (float2*)smraw;                 // [w*32 + kx], w in [0,64]
    float4* s_t4  = (float4*)(s_cs + 65 * 32);      // [n] = (c, c, s, s)
    float*  s_raw = (float*)(s_t4 + 256);           // raw chunk [32][256]
    u64x2*  s_xq  = (u64x2*)(s_raw + 32 * 256);     // [r*65 + w]
    u64*    s_x64 = (u64*)(s_xq + 32 * 65);         // [r]
    u64*    s_DA  = s_x64 + 32;                     // [r*32 + kx] chunk c
    u64*    s_DB  = s_DA + 32 * 32;                 // chunk c+4

    const int t  = threadIdx.x;
    const int bi = blockIdx.x;
    const float* xp = x + (size_t)bi * (Hn * Wn);

    const unsigned raw_base = smem_u32(s_raw);
    // chunk visit order: 0,4,1,5,2,6,3,7  ->  ((s&1)<<2) | (s>>1)
    {
        #pragma unroll
        for (int j = 0; j < 8; ++j) {
            int e = t + j * 256;
            const float* src = xp + e * 4;          // chunk 0
            unsigned dst = raw_base + e * 16;
            asm volatile("cp.async.ca.shared.global [%0], [%1], 16;"
                         :: "r"(dst), "l"(src));
        }
        asm volatile("cp.async.commit_group;");
    }

    for (int idx = t; idx < 65 * 32; idx += 256) {
        int w = idx >> 5, kx = idx & 31;
        float sv, cv;
        sincospif(((w * kx) & 255) * (2.0f / 256.0f), &sv, &cv);
        s_cs[idx] = make_float2(cv, -sv);
    }
    {
        float sv, cv;
        sincospif(t * (2.0f / 256.0f), &sv, &cv);
        s_t4[t] = make_float4(cv, cv, sv, sv);
    }

    const int warp = t >> 5, lane = t & 31;
    const int kxg  = warp & 1;
    const int rg   = warp >> 1;
    const int kl   = lane & 7;
    const int rl   = lane >> 3;
    const int kx0  = kxg * 16 + kl * 2;      // even
    const int row0 = rg * 8 + rl * 2;        // EVEN ky; row0+1 odd

    u64 X[2][2];
    X[0][0] = X[0][1] = X[1][0] = X[1][1] = 0ull;

    const u64* cs64 = (const u64*)s_cs;

    asm volatile("cp.async.wait_group 0;");
    __syncthreads();

    for (int s = 0; s < 8; ++s) {
        // ---- fold raw (smem) -> xq / x64
        #pragma unroll 2
        for (int idx = t; idx < 32 * 64; idx += 256) {
            int r = idx >> 6;
            int w = idx & 63;
            const float* row = s_raw + r * 256;
            u64x2 v;
            if (w == 0) {
                float x0 = row[0], x128 = row[128];
                v.x = f2u(x0 + x128, 0.f);
                v.y = f2u(x0 - x128, 0.f);
            } else {
                float xa = row[w],       xb = row[256 - w];
                float xc = row[128 - w], xd = row[128 + w];
                v.x = f2u(xa + xb + xc + xd, xa - xb - xc + xd);
                v.y = f2u(xa + xb - xc - xd, xa - xb + xc - xd);
            }
            s_xq[r * 65 + w] = v;
        }
        if (t < 32) {
            const float* row = s_raw + t * 256;
            float a = row[64], b = row[192];
            s_x64[t] = f2u(a + b, a - b);
        }
        __syncthreads();   // raw consumed, xq ready

        // ---- prefetch next chunk
        if (s < 7) {
            int nc = (((s + 1) & 1) << 2) | ((s + 1) >> 1);
            const float* xc = xp + (size_t)nc * 32 * Wn;
            #pragma unroll
            for (int j = 0; j < 8; ++j) {
                int e = t + j * 256;
                const float* src = xc + e * 4;
                unsigned dst = raw_base + e * 16;
                asm volatile("cp.async.ca.shared.global [%0], [%1], 16;"
                             :: "r"(dst), "l"(src));
            }
            asm volatile("cp.async.commit_group;");
        }

        // ---- stage 1: quarter-folded row DFT -> D_A (even s) or D_B (odd s)
        {
            u64* sD = (s & 1) ? s_DB : s_DA;
            u64 a00 = 0ull, a01 = 0ull, a10 = 0ull, a11 = 0ull;
            #pragma unroll 4
            for (int w = 0; w < 64; ++w) {
                u64x2 tw = *(const u64x2*)&cs64[w * 32 + kx0];
                u64x2 v0 = s_xq[row0 * 65 + w];
                u64x2 v1 = s_xq[(row0 + 1) * 65 + w];
                a00 = ffma2(v0.x, tw.x, a00);
                a01 = ffma2(v0.y, tw.y, a01);
                a10 = ffma2(v1.x, tw.x, a10);
                a11 = ffma2(v1.y, tw.y, a11);
            }
            {
                u64x2 tw = *(const u64x2*)&cs64[64 * 32 + kx0];
                u64 v0 = s_x64[row0];
                u64 v1 = s_x64[row0 + 1];
                a00 = ffma2(v0, tw.x, a00);
                a01 = ffma2(v0, tw.y, a01);
                a10 = ffma2(v1, tw.x, a10);
                a11 = ffma2(v1, tw.y, a11);
            }
            u64x2 p0; p0.x = a00; p0.y = a01;
            u64x2 p1; p1.x = a10; p1.y = a11;
            *(u64x2*)&sD[row0 * 32 + kx0]       = p0;
            *(u64x2*)&sD[(row0 + 1) * 32 + kx0] = p1;
        }
        __syncthreads();   // D ready; xq free

        // ---- stage 2 on pair (c, c+4): h in [cp*32, cp*32+31], fold h vs h+128
        if (s & 1) {
            const int h0 = (s >> 1) * 32;
            #pragma unroll 4
            for (int r = 0; r < 32; ++r) {
                const int h = h0 + r;
                u64x2 dA = *(const u64x2*)&s_DA[r * 32 + kx0];
                u64x2 dB = *(const u64x2*)&s_DB[r * 32 + kx0];
                u64 ds0 = fadd2(dA.x, dB.x), ds1 = fadd2(dA.y, dB.y);
                u64 dd0 = fsub2(dA.x, dB.x), dd1 = fsub2(dA.y, dB.y);
                float2 f0 = u2f(ds0), f1 = u2f(ds1);
                float2 g0 = u2f(dd0), g1 = u2f(dd1);
                u64 qs0 = f2u(f0.y, -f0.x), qs1 = f2u(f1.y, -f1.x);
                u64 qd0 = f2u(g0.y, -g0.x), qd1 = f2u(g1.y, -g1.x);
                u64x2 e0 = *(const u64x2*)&s_t4[(row0 * h) & 255];
                u64x2 e1 = *(const u64x2*)&s_t4[((row0 + 1) * h) & 255];
                X[0][0] = ffma2(ds0, e0.x, X[0][0]);
                X[0][0] = ffma2(qs0, e0.y, X[0][0]);
                X[0][1] = ffma2(ds1, e0.x, X[0][1]);
                X[0][1] = ffma2(qs1, e0.y, X[0][1]);
                X[1][0] = ffma2(dd0, e1.x, X[1][0]);
                X[1][0] = ffma2(qd0, e1.y, X[1][0]);
                X[1][1] = ffma2(dd1, e1.x, X[1][1]);
                X[1][1] = ffma2(qd1, e1.y, X[1][1]);
            }
        }
        if (s < 7) asm volatile("cp.async.wait_group 0;");
        __syncthreads();
    }

    #pragma unroll
    for (int j = 0; j < 2; ++j)
        #pragma unroll
        for (int i = 0; i < 2; ++i)
            g_X[(size_t)bi * 1024 + (row0 + j) * 32 + kx0 + i] = X[j][i];
}

// ---------------------------------------------------------------------------
// Mix (unchanged)
// ---------------------------------------------------------------------------
__global__ __launch_bounds__(256) void mix_kernel(const float* __restrict__ wts) {
    __shared__ float s_W[CIN * COUT];
    __shared__ u64   s_X[Bn * CIN];
    const int t = threadIdx.x;
    const int m = blockIdx.x;

    for (int e = t; e < CIN * COUT; e += 256)
        s_W[e] = wts[(size_t)e * 1024 + m];
    for (int e = t; e < Bn * CIN; e += 256)
        s_X[e] = g_X[(size_t)e * 1024 + m];
    __syncthreads();

    const int o  = t & 63;
    const int bq = t >> 6;
    u64 acc[4] = {0ull, 0ull, 0ull, 0ull};

    #pragma unroll 8
    for (int i = 0; i < CIN; ++i) {
        float wv = s_W[i * 64 + o];
        u64 wp = f2u(wv, wv);
        #pragma unroll
        for (int j = 0; j < 4; ++j)
            acc[j] = ffma2(s_X[(bq * 4 + j) * 64 + i], wp, acc[j]);
    }
    #pragma unroll
    for (int j = 0; j < 4; ++j)
        g_S[((size_t)(bq * 4 + j) * 64 + o) * 1024 + m] = acc[j];
}

// ---------------------------------------------------------------------------
// Inverse v3: C1 ky-parity fold (chunk pairs c, c+8: 4 G rows per 2-row cost)
// + kk-parity folded C2 (from R10).
// smem: tw[32][65] u64x2 | t4i[256] f4 | S[1024] u64 | G2a[32*9] | G2b[32*9]
//       total 54784 B  -> 4 blocks/SM
// ---------------------------------------------------------------------------
#define INV_SMEM_BYTES (32*65*16 + 256*16 + 1024*8 + 2*32*9*16)

__global__ __launch_bounds__(256) void inv_kernel(const float* __restrict__ bias,
                                                  float* __restrict__ out) {
    extern __shared__ char smraw[];
    u64x2*  s_tw  = (u64x2*)smraw;                  // [kk*65 + w]
    float4* s_t4i = (float4*)(s_tw + 32 * 65);      // [n] = (c, s, -s, c)
    u64*    s_S   = (u64*)(s_t4i + 256);            // [ky*32 + kx], pre-scaled
    u64x2*  s_G2a = (u64x2*)(s_S + 1024);           // [kk*9 + rp]  rows hb..hb+15
    u64x2*  s_G2b = s_G2a + 32 * 9;                 // rows hb+128..hb+143

    const int t  = threadIdx.x;
    const int bo = blockIdx.x;
    const int o  = bo & 63;

    for (int idx = t; idx < 32 * 65; idx += 256) {
        int kk = idx / 65;
        int w  = idx - kk * 65;
        float sv, cv;
        sincospif(((kk * w) & 255) * (2.0f / 256.0f), &sv, &cv);
        u64x2 e; e.x = f2u(cv, cv); e.y = f2u(sv, sv);
        s_tw[idx] = e;
    }
    {
        float sv, cv;
        sincospif(t * (2.0f / 256.0f), &sv, &cv);
        s_t4i[t] = make_float4(cv, sv, -sv, cv);
    }
    for (int e = t; e < 1024; e += 256) {
        float2 v  = u2f(g_S[(size_t)bo * 1024 + e]);
        float sc  = ((e & 31) == 0 ? 1.f : 2.f) * (1.f / 65536.f);
        s_S[e] = f2u(v.x * sc, v.y * sc);
    }
    const float bias_o = bias[o];
    const u64 b2 = f2u(bias_o, bias_o);
    __syncthreads();

    // C1 mapping: lane = kx, warp = r2 (rows h1, h1+8, h1+128, h1+136)
    const int kx = t & 31, r2 = t >> 5;
    // C2 mapping: w = t&63, rpg = t>>6 (rp, rp+4)
    const int w   = t & 63;
    const int rpg = t >> 6;
    const int rp0 = rpg, rp1 = rpg + 4;

    float* yp = out + (size_t)bo * (Hn * Wn);

    for (int cp = 0; cp < 8; ++cp) {
        const int hbA = cp * 16;          // paired with hbA + 128

        // ---- C1 (folded): even/odd-ky partial sums -> rows h1, h1+8, h1+128, h1+136
        {
            const int h1 = hbA + r2;
            const int h2 = h1 + 8;
            u64 aE1 = 0ull, aO1 = 0ull, aE2 = 0ull, aO2 = 0ull;
            #pragma unroll 4
            for (int ky = 0; ky < 32; ky += 2) {
                float2 sv = u2f(s_S[ky * 32 + kx]);
                u64 sxx = f2u(sv.x, sv.x);
                u64 syy = f2u(sv.y, sv.y);
                u64x2 e1 = *(const u64x2*)&s_t4i[(ky * h1) & 255];
                u64x2 e2 = *(const u64x2*)&s_t4i[(ky * h2) & 255];
                aE1 = ffma2(sxx, e1.x, aE1);
                aE1 = ffma2(syy, e1.y, aE1);
                aE2 = ffma2(sxx, e2.x, aE2);
                aE2 = ffma2(syy, e2.y, aE2);
                float2 sw = u2f(s_S[(ky + 1) * 32 + kx]);
                u64 txx = f2u(sw.x, sw.x);
                u64 tyy = f2u(sw.y, sw.y);
                u64x2 f1 = *(const u64x2*)&s_t4i[((ky + 1) * h1) & 255];
                u64x2 f2v = *(const u64x2*)&s_t4i[((ky + 1) * h2) & 255];
                aO1 = ffma2(txx, f1.x, aO1);
                aO1 = ffma2(tyy, f1.y, aO1);
                aO2 = ffma2(txx, f2v.x, aO2);
                aO2 = ffma2(tyy, f2v.y, aO2);
            }
            u64 a1 = fadd2(aE1, aO1), a2 = fadd2(aE2, aO2);   // rows h1, h1+8
            u64 a3 = fsub2(aE1, aO1), a4 = fsub2(aE2, aO2);   // rows +128
            float2 A1 = u2f(a1), A2 = u2f(a2), A3 = u2f(a3), A4 = u2f(a4);
            u64x2 ga; ga.x = f2u(A1.x, A2.x); ga.y = f2u(A1.y, A2.y);
            u64x2 gb; gb.x = f2u(A3.x, A4.x); gb.y = f2u(A3.y, A4.y);
            s_G2a[kx * 9 + r2] = ga;
            s_G2b[kx * 9 + r2] = gb;
        }
        __syncthreads();

        // ---- C2 twice: half=0 -> rows hbA.., half=1 -> rows hbA+128..
        #pragma unroll
        for (int half = 0; half < 2; ++half) {
            const u64x2* G2 = half ? s_G2b : s_G2a;
            const int hb = hbA + half * 128;

            u64 Ce0 = 0ull, Se0 = 0ull, Co0 = 0ull, So0 = 0ull;
            u64 Ce1 = 0ull, Se1 = 0ull, Co1 = 0ull, So1 = 0ull;
            #pragma unroll 8
            for (int kk = 0; kk < 32; kk += 2) {
                u64x2 twE = s_tw[kk * 65 + w];
                u64x2 twO = s_tw[(kk + 1) * 65 + w];
                u64x2 gE0 = G2[kk * 9 + rp0];
                u64x2 gO0 = G2[(kk + 1) * 9 + rp0];
                u64x2 gE1 = G2[kk * 9 + rp1];
                u64x2 gO1 = G2[(kk + 1) * 9 + rp1];
                Ce0 = ffma2(gE0.x, twE.x, Ce0);
                Se0 = ffma2(gE0.y, twE.y, Se0);
                Co0 = ffma2(gO0.x, twO.x, Co0);
                So0 = ffma2(gO0.y, twO.y, So0);
                Ce1 = ffma2(gE1.x, twE.x, Ce1);
                Se1 = ffma2(gE1.y, twE.y, Se1);
                Co1 = ffma2(gO1.x, twO.x, Co1);
                So1 = ffma2(gO1.y, twO.y, So1);
            }
            #pragma unroll
            for (int p = 0; p < 2; ++p) {
                u64 Ce = p ? Ce1 : Ce0, Co = p ? Co1 : Co0;
                u64 Se = p ? Se1 : Se0, So = p ? So1 : So0;
                const int rp = p ? rp1 : rp0;
                const int hA = hb + rp, hB = hA + 8;
                u64 P = fadd2(Ce, Co), Q = fadd2(Se, So);
                u64 R = fsub2(Ce, Co), T = fsub2(Se, So);
                float2 yw  = u2f(fadd2(fsub2(P, Q), b2));   // col w
                float2 ymw = u2f(fadd2(fadd2(P, Q), b2));   // col 256-w
                float2 yr  = u2f(fadd2(fadd2(R, T), b2));   // col 128-w
                float2 yrw = u2f(fadd2(fsub2(R, T), b2));   // col 128+w
                yp[hA * 256 + w] = yw.x;
                yp[hB * 256 + w] = yw.y;
                yp[hA * 256 + ((256 - w) & 255)] = ymw.x;
                yp[hB * 256 + ((256 - w) & 255)] = ymw.y;
                yp[hA * 256 + (128 - w)] = yr.x;
                yp[hB * 256 + (128 - w)] = yr.y;
                yp[hA * 256 + (128 + w)] = yrw.x;
                yp[hB * 256 + (128 + w)] = yrw.y;
            }

            if (w == 0) {
                u64 A0 = 0ull, B0 = 0ull, A1v = 0ull, B1v = 0ull;
                #pragma unroll
                for (int m = 0; m < 16; m += 2) {
                    A0  = fadd2(A0,  G2[(2 * m) * 9 + rp0].x);
                    B0  = fadd2(B0,  G2[(2 * m + 1) * 9 + rp0].y);
                    A0  = fsub2(A0,  G2[(2 * m + 2) * 9 + rp0].x);
                    B0  = fsub2(B0,  G2[(2 * m + 3) * 9 + rp0].y);
                    A1v = fadd2(A1v, G2[(2 * m) * 9 + rp1].x);
                    B1v = fadd2(B1v, G2[(2 * m + 1) * 9 + rp1].y);
                    A1v = fsub2(A1v, G2[(2 * m + 2) * 9 + rp1].x);
                    B1v = fsub2(B1v, G2[(2 * m + 3) * 9 + rp1].y);
                }
                #pragma unroll
                for (int p = 0; p < 2; ++p) {
                    u64 A = p ? A1v : A0, Bv = p ? B1v : B0;
                    const int rp = p ? rp1 : rp0;
                    const int hA = hb + rp, hB = hA + 8;
                    float2 y64  = u2f(fadd2(fsub2(A, Bv), b2));
                    float2 y192 = u2f(fadd2(fadd2(A, Bv), b2));
                    yp[hA * 256 + 64]  = y64.x;
                    yp[hB * 256 + 64]  = y64.y;
                    yp[hA * 256 + 192] = y192.x;
                    yp[hB * 256 + 192] = y192.y;
                }
            }
        }
        __syncthreads();
    }
}

// ---------------------------------------------------------------------------
extern "C" void kernel_launch(void* const* d_in, const int* in_sizes, int n_in,
                              void* d_out, int out_size) {
    const float* x    = (const float*)d_in[0];
    const float* wts  = (const float*)d_in[1];
    const float* bias = (const float*)d_in[2];
    float* out = (float*)d_out;

    cudaFuncSetAttribute(fwd_kernel, cudaFuncAttributeMaxDynamicSharedMemorySize,
                         FWD_SMEM_BYTES);
    cudaFuncSetAttribute(inv_kernel, cudaFuncAttributeMaxDynamicSharedMemorySize,
                         INV_SMEM_BYTES);

    fwd_kernel<<<Bn * CIN, 256, FWD_SMEM_BYTES>>>(x);
    mix_kernel<<<1024, 256>>>(wts);
    inv_kernel<<<Bn * COUT, 256, INV_SMEM_BYTES>>>(bias, out);
}

// round 13
// speedup vs baseline: 2.0217x; 1.2462x over previous
#include <cuda_runtime.h>
#include <math.h>

typedef unsigned long long u64;
typedef ulonglong2 u64x2;

#define Hn   256
#define Wn   256
#define CIN  64
#define COUT 64
#define Bn   16

__device__ __forceinline__ u64 f2u(float lo, float hi) {
    u64 r; asm("mov.b64 %0, {%1,%2};" : "=l"(r) : "f"(lo), "f"(hi)); return r;
}
__device__ __forceinline__ float2 u2f(u64 v) {
    float2 r; asm("mov.b64 {%0,%1}, %2;" : "=f"(r.x), "=f"(r.y) : "l"(v)); return r;
}
__device__ __forceinline__ u64 ffma2(u64 a, u64 b, u64 c) {
    u64 d; asm("fma.rn.f32x2 %0, %1, %2, %3;" : "=l"(d) : "l"(a), "l"(b), "l"(c));
    return d;
}
__device__ __forceinline__ u64 fadd2(u64 a, u64 b) {
    u64 d; asm("add.rn.f32x2 %0, %1, %2;" : "=l"(d) : "l"(a), "l"(b));
    return d;
}
__device__ __forceinline__ u64 fsub2(u64 a, u64 b) {
    return fadd2(a, b ^ 0x8000000080000000ull);
}
__device__ __forceinline__ unsigned smem_u32(const void* p) {
    unsigned a;
    asm("{ .reg .u64 t; cvta.to.shared.u64 t, %1; cvt.u32.u64 %0, t; }"
        : "=r"(a) : "l"(p));
    return a;
}

// Intermediate spectra, packed (re, im) in one u64
__device__ u64 g_X[Bn * CIN * 1024];
__device__ u64 g_S[Bn * COUT * 1024];
// Transposed weights: [mode][io]
__device__ float g_Wt[1024 * 4096];

// ---------------------------------------------------------------------------
// Weight transpose: wts[io][m] -> g_Wt[m][io]
// ---------------------------------------------------------------------------
__global__ __launch_bounds__(256) void transpose_w(const float* __restrict__ wts) {
    __shared__ float tile[32][33];
    const int tx = threadIdx.x & 31, ty = threadIdx.x >> 5;   // 32 x 8
    const int io0 = blockIdx.x * 32;
    const int m0  = blockIdx.y * 32;
    #pragma unroll
    for (int j = ty; j < 32; j += 8)
        tile[j][tx] = wts[(size_t)(io0 + j) * 1024 + m0 + tx];
    __syncthreads();
    #pragma unroll
    for (int j = ty; j < 32; j += 8)
        g_Wt[(size_t)(m0 + j) * 4096 + io0 + tx] = tile[tx][j];
}

// ---------------------------------------------------------------------------
// Forward v5 (R9, proven 224.6us): quarter-fold + cp.async pipeline
// ---------------------------------------------------------------------------
#define FWD_SMEM_BYTES (65*32*8 + 256*16 + 32*256*4 + 32*65*16 + 32*8 + 32*32*8)

__global__ __launch_bounds__(256, 2) void fwd_kernel(const float* __restrict__ x) {
    extern __shared__ char smraw[];
    float2* s_cs  = (float2*)smraw;
    float4* s_t4  = (float4*)(s_cs + 65 * 32);
    float*  s_raw = (float*)(s_t4 + 256);
    u64x2*  s_xq  = (u64x2*)(s_raw + 32 * 256);
    u64*    s_x64 = (u64*)(s_xq + 32 * 65);
    u64*    s_D   = s_x64 + 32;

    const int t  = threadIdx.x;
    const int bi = blockIdx.x;
    const float* xp = x + (size_t)bi * (Hn * Wn);

    const unsigned raw_base = smem_u32(s_raw);
    {
        #pragma unroll
        for (int j = 0; j < 8; ++j) {
            int e = t + j * 256;
            const float* src = xp + e * 4;
            unsigned dst = raw_base + e * 16;
            asm volatile("cp.async.ca.shared.global [%0], [%1], 16;"
                         :: "r"(dst), "l"(src));
        }
        asm volatile("cp.async.commit_group;");
    }

    for (int idx = t; idx < 65 * 32; idx += 256) {
        int w = idx >> 5, kx = idx & 31;
        float sv, cv;
        sincospif(((w * kx) & 255) * (2.0f / 256.0f), &sv, &cv);
        s_cs[idx] = make_float2(cv, -sv);
    }
    {
        float sv, cv;
        sincospif(t * (2.0f / 256.0f), &sv, &cv);
        s_t4[t] = make_float4(cv, cv, sv, sv);
    }

    const int warp = t >> 5, lane = t & 31;
    const int kxg  = warp & 1;
    const int rg   = warp >> 1;
    const int kl   = lane & 7;
    const int rl   = lane >> 3;
    const int kx0  = kxg * 16 + kl * 2;
    const int row0 = rg * 8 + rl * 2;

    u64 X[2][2];
    X[0][0] = X[0][1] = X[1][0] = X[1][1] = 0ull;

    const u64* cs64 = (const u64*)s_cs;

    asm volatile("cp.async.wait_group 0;");
    __syncthreads();

    for (int c = 0; c < 8; ++c) {
        #pragma unroll 2
        for (int idx = t; idx < 32 * 64; idx += 256) {
            int r = idx >> 6;
            int w = idx & 63;
            const float* row = s_raw + r * 256;
            u64x2 v;
            if (w == 0) {
                float x0 = row[0], x128 = row[128];
                v.x = f2u(x0 + x128, 0.f);
                v.y = f2u(x0 - x128, 0.f);
            } else {
                float xa = row[w],       xb = row[256 - w];
                float xc = row[128 - w], xd = row[128 + w];
                v.x = f2u(xa + xb + xc + xd, xa - xb - xc + xd);
                v.y = f2u(xa + xb - xc - xd, xa - xb + xc - xd);
            }
            s_xq[r * 65 + w] = v;
        }
        if (t < 32) {
            const float* row = s_raw + t * 256;
            float a = row[64], b = row[192];
            s_x64[t] = f2u(a + b, a - b);
        }
        __syncthreads();

        if (c < 7) {
            const float* xc = xp + (size_t)(c + 1) * 32 * Wn;
            #pragma unroll
            for (int j = 0; j < 8; ++j) {
                int e = t + j * 256;
                const float* src = xc + e * 4;
                unsigned dst = raw_base + e * 16;
                asm volatile("cp.async.ca.shared.global [%0], [%1], 16;"
                             :: "r"(dst), "l"(src));
            }
            asm volatile("cp.async.commit_group;");
        }

        {
            u64 a00 = 0ull, a01 = 0ull, a10 = 0ull, a11 = 0ull;
            #pragma unroll 4
            for (int w = 0; w < 64; ++w) {
                u64x2 tw = *(const u64x2*)&cs64[w * 32 + kx0];
                u64x2 v0 = s_xq[row0 * 65 + w];
                u64x2 v1 = s_xq[(row0 + 1) * 65 + w];
                a00 = ffma2(v0.x, tw.x, a00);
                a01 = ffma2(v0.y, tw.y, a01);
                a10 = ffma2(v1.x, tw.x, a10);
                a11 = ffma2(v1.y, tw.y, a11);
            }
            {
                u64x2 tw = *(const u64x2*)&cs64[64 * 32 + kx0];
                u64 v0 = s_x64[row0];
                u64 v1 = s_x64[row0 + 1];
                a00 = ffma2(v0, tw.x, a00);
                a01 = ffma2(v0, tw.y, a01);
                a10 = ffma2(v1, tw.x, a10);
                a11 = ffma2(v1, tw.y, a11);
            }
            u64x2 p0; p0.x = a00; p0.y = a01;
            u64x2 p1; p1.x = a10; p1.y = a11;
            *(u64x2*)&s_D[row0 * 32 + kx0]       = p0;
            *(u64x2*)&s_D[(row0 + 1) * 32 + kx0] = p1;
        }
        __syncthreads();

        const int h0 = c * 32;
        #pragma unroll 4
        for (int r = 0; r < 32; ++r) {
            const int h = h0 + r;
            u64x2 dp = *(const u64x2*)&s_D[r * 32 + kx0];
            float2 d0 = u2f(dp.x), d1 = u2f(dp.y);
            u64 dq0 = f2u(d0.y, -d0.x);
            u64 dq1 = f2u(d1.y, -d1.x);
            u64x2 e0 = *(const u64x2*)&s_t4[(row0 * h) & 255];
            u64x2 e1 = *(const u64x2*)&s_t4[((row0 + 1) * h) & 255];
            X[0][0] = ffma2(dp.x, e0.x, X[0][0]);
            X[0][0] = ffma2(dq0,  e0.y, X[0][0]);
            X[0][1] = ffma2(dp.y, e0.x, X[0][1]);
            X[0][1] = ffma2(dq1,  e0.y, X[0][1]);
            X[1][0] = ffma2(dp.x, e1.x, X[1][0]);
            X[1][0] = ffma2(dq0,  e1.y, X[1][0]);
            X[1][1] = ffma2(dp.y, e1.x, X[1][1]);
            X[1][1] = ffma2(dq1,  e1.y, X[1][1]);
        }
        if (c < 7) asm volatile("cp.async.wait_group 0;");
        __syncthreads();
    }

    #pragma unroll
    for (int j = 0; j < 2; ++j)
        #pragma unroll
        for (int i = 0; i < 2; ++i)
            g_X[(size_t)bi * 1024 + (row0 + j) * 32 + kx0 + i] = X[j][i];
}

// ---------------------------------------------------------------------------
// Mix: coalesced transposed-weight loads
// ---------------------------------------------------------------------------
__global__ __launch_bounds__(256) void mix_kernel() {
    __shared__ float s_W[CIN * COUT];
    __shared__ u64   s_X[Bn * CIN];
    const int t = threadIdx.x;
    const int m = blockIdx.x;

    {
        const float4* wp4 = (const float4*)(g_Wt + (size_t)m * 4096);
        #pragma unroll
        for (int e = t; e < 1024; e += 256)
            ((float4*)s_W)[e] = wp4[e];
    }
    for (int e = t; e < Bn * CIN; e += 256)
        s_X[e] = g_X[(size_t)e * 1024 + m];
    __syncthreads();

    const int o  = t & 63;
    const int bq = t >> 6;
    u64 acc[4] = {0ull, 0ull, 0ull, 0ull};

    #pragma unroll 8
    for (int i = 0; i < CIN; ++i) {
        float wv = s_W[i * 64 + o];
        u64 wp = f2u(wv, wv);
        #pragma unroll
        for (int j = 0; j < 4; ++j)
            acc[j] = ffma2(s_X[(bq * 4 + j) * 64 + i], wp, acc[j]);
    }
    #pragma unroll
    for (int j = 0; j < 4; ++j)
        g_S[((size_t)(bq * 4 + j) * 64 + o) * 1024 + m] = acc[j];
}

// ---------------------------------------------------------------------------
// Inverse v4: C1 ky-parity fold (adjacent-row pairs) + merged-half C2 with
// compact (c,s) twiddles and the packed (gR*c, gI*s) ffma2 identity.
// smem: ci[32][68] f2 (c,s) | t4i[256] f4 | S[1024] u64 |
//       Ga[32*18] u64 | Gb[32*18] u64          total 38912 B
// ---------------------------------------------------------------------------
#define INV_SMEM_BYTES (32*68*8 + 256*16 + 1024*8 + 2*32*18*8)

__global__ __launch_bounds__(256) void inv_kernel(const float* __restrict__ bias,
                                                  float* __restrict__ out) {
    extern __shared__ char smraw[];
    float2* s_ci  = (float2*)smraw;                 // [kk*68 + w], w in [0,64]
    float4* s_t4i = (float4*)(s_ci + 32 * 68);      // [n] = (c, s, -s, c)
    u64*    s_S   = (u64*)(s_t4i + 256);            // [ky*32 + kx], pre-scaled
    u64*    s_Ga  = s_S + 1024;                     // [kk*18 + r], r in 0..15
    u64*    s_Gb  = s_Ga + 32 * 18;

    const int t  = threadIdx.x;
    const int bo = blockIdx.x;
    const int o  = bo & 63;

    for (int idx = t; idx < 32 * 65; idx += 256) {
        int kk = idx / 65;
        int w  = idx - kk * 65;
        float sv, cv;
        sincospif(((kk * w) & 255) * (2.0f / 256.0f), &sv, &cv);
        s_ci[kk * 68 + w] = make_float2(cv, sv);
    }
    {
        float sv, cv;
        sincospif(t * (2.0f / 256.0f), &sv, &cv);
        s_t4i[t] = make_float4(cv, sv, -sv, cv);
    }
    for (int e = t; e < 1024; e += 256) {
        float2 v  = u2f(g_S[(size_t)bo * 1024 + e]);
        float sc  = ((e & 31) == 0 ? 1.f : 2.f) * (1.f / 65536.f);
        s_S[e] = f2u(v.x * sc, v.y * sc);
    }
    const float bias_o = bias[o];
    __syncthreads();

    // C1 mapping: lane = kx, warp r2: rows (2r2, 2r2+1) and +128 twins
    const int kx = t & 31, r2 = t >> 5;
    // C2 mapping: wp -> cols (2wp, 2wp+1) & mirrors; rpg -> 4 rows; half
    const int wp   = t & 31;
    const int w0   = wp * 2;
    const int rpg  = (t >> 5) & 3;
    const int half = t >> 7;
    const int r0   = rpg * 4;

    float* yp = out + (size_t)bo * (Hn * Wn);
    const u64* Gh = half ? s_Gb : s_Ga;

    for (int cp = 0; cp < 8; ++cp) {
        const int hbA = cp * 16;

        // ---- C1 (ky-parity folded): rows h1=hbA+2r2, h1+1, and +128 twins
        {
            const int h1 = hbA + 2 * r2;
            const int h2 = h1 + 1;
            u64 aE1 = 0ull, aO1 = 0ull, aE2 = 0ull, aO2 = 0ull;
            #pragma unroll 4
            for (int ky = 0; ky < 32; ky += 2) {
                float2 sv = u2f(s_S[ky * 32 + kx]);
                u64 sxx = f2u(sv.x, sv.x);
                u64 syy = f2u(sv.y, sv.y);
                u64x2 e1 = *(const u64x2*)&s_t4i[(ky * h1) & 255];
                u64x2 e2 = *(const u64x2*)&s_t4i[(ky * h2) & 255];
                aE1 = ffma2(sxx, e1.x, aE1);
                aE1 = ffma2(syy, e1.y, aE1);
                aE2 = ffma2(sxx, e2.x, aE2);
                aE2 = ffma2(syy, e2.y, aE2);
                float2 sw = u2f(s_S[(ky + 1) * 32 + kx]);
                u64 txx = f2u(sw.x, sw.x);
                u64 tyy = f2u(sw.y, sw.y);
                u64x2 f1  = *(const u64x2*)&s_t4i[((ky + 1) * h1) & 255];
                u64x2 f2v = *(const u64x2*)&s_t4i[((ky + 1) * h2) & 255];
                aO1 = ffma2(txx, f1.x, aO1);
                aO1 = ffma2(tyy, f1.y, aO1);
                aO2 = ffma2(txx, f2v.x, aO2);
                aO2 = ffma2(tyy, f2v.y, aO2);
            }
            u64x2 ga; ga.x = fadd2(aE1, aO1); ga.y = fadd2(aE2, aO2);
            u64x2 gb; gb.x = fsub2(aE1, aO1); gb.y = fsub2(aE2, aO2);
            *(u64x2*)&s_Ga[kx * 18 + 2 * r2] = ga;
            *(u64x2*)&s_Gb[kx * 18 + 2 * r2] = gb;
        }
        __syncthreads();

        // ---- C2: merged halves, 2 w x 4 rows x 2 kk-parities per thread
        {
            const int hb = hbA + half * 128;
            u64 aE[2][4], aO[2][4];
            float A[4], B[4];
            #pragma unroll
            for (int wv = 0; wv < 2; ++wv)
                #pragma unroll
                for (int r = 0; r < 4; ++r) { aE[wv][r] = 0ull; aO[wv][r] = 0ull; }
            #pragma unroll
            for (int r = 0; r < 4; ++r) { A[r] = 0.f; B[r] = 0.f; }

            #pragma unroll 4
            for (int kk = 0; kk < 32; kk += 4) {
                // ---- kk-pair (kk, kk+1), A/B sign +
                {
                    u64x2 twE = *(const u64x2*)&s_ci[kk * 68 + w0];
                    u64x2 twO = *(const u64x2*)&s_ci[(kk + 1) * 68 + w0];
                    u64x2 gEa = *(const u64x2*)&Gh[kk * 18 + r0];
                    u64x2 gEb = *(const u64x2*)&Gh[kk * 18 + r0 + 2];
                    u64x2 gOa = *(const u64x2*)&Gh[(kk + 1) * 18 + r0];
                    u64x2 gOb = *(const u64x2*)&Gh[(kk + 1) * 18 + r0 + 2];
                    aE[0][0] = ffma2(gEa.x, twE.x, aE[0][0]);
                    aE[0][1] = ffma2(gEa.y, twE.x, aE[0][1]);
                    aE[0][2] = ffma2(gEb.x, twE.x, aE[0][2]);
                    aE[0][3] = ffma2(gEb.y, twE.x, aE[0][3]);
                    aE[1][0] = ffma2(gEa.x, twE.y, aE[1][0]);
                    aE[1][1] = ffma2(gEa.y, twE.y, aE[1][1]);
                    aE[1][2] = ffma2(gEb.x, twE.y, aE[1][2]);
                    aE[1][3] = ffma2(gEb.y, twE.y, aE[1][3]);
                    aO[0][0] = ffma2(gOa.x, twO.x, aO[0][0]);
                    aO[0][1] = ffma2(gOa.y, twO.x, aO[0][1]);
                    aO[0][2] = ffma2(gOb.x, twO.x, aO[0][2]);
                    aO[0][3] = ffma2(gOb.y, twO.x, aO[0][3]);
                    aO[1][0] = ffma2(gOa.x, twO.y, aO[1][0]);
                    aO[1][1] = ffma2(gOa.y, twO.y, aO[1][1]);
                    aO[1][2] = ffma2(gOb.x, twO.y, aO[1][2]);
                    aO[1][3] = ffma2(gOb.y, twO.y, aO[1][3]);
                    A[0] += u2f(gEa.x).x; A[1] += u2f(gEa.y).x;
                    A[2] += u2f(gEb.x).x; A[3] += u2f(gEb.y).x;
                    B[0] += u2f(gOa.x).y; B[1] += u2f(gOa.y).y;
                    B[2] += u2f(gOb.x).y; B[3] += u2f(gOb.y).y;
                }
                // ---- kk-pair (kk+2, kk+3), A/B sign -
                {
                    u64x2 twE = *(const u64x2*)&s_ci[(kk + 2) * 68 + w0];
                    u64x2 twO = *(const u64x2*)&s_ci[(kk + 3) * 68 + w0];
                    u64x2 gEa = *(const u64x2*)&Gh[(kk + 2) * 18 + r0];
                    u64x2 gEb = *(const u64x2*)&Gh[(kk + 2) * 18 + r0 + 2];
                    u64x2 gOa = *(const u64x2*)&Gh[(kk + 3) * 18 + r0];
                    u64x2 gOb = *(const u64x2*)&Gh[(kk + 3) * 18 + r0 + 2];
                    aE[0][0] = ffma2(gEa.x, twE.x, aE[0][0]);
                    aE[0][1] = ffma2(gEa.y, twE.x, aE[0][1]);
                    aE[0][2] = ffma2(gEb.x, twE.x, aE[0][2]);
                    aE[0][3] = ffma2(gEb.y, twE.x, aE[0][3]);
                    aE[1][0] = ffma2(gEa.x, twE.y, aE[1][0]);
                    aE[1][1] = ffma2(gEa.y, twE.y, aE[1][1]);
                    aE[1][2] = ffma2(gEb.x, twE.y, aE[1][2]);
                    aE[1][3] = ffma2(gEb.y, twE.y, aE[1][3]);
                    aO[0][0] = ffma2(gOa.x, twO.x, aO[0][0]);
                    aO[0][1] = ffma2(gOa.y, twO.x, aO[0][1]);
                    aO[0][2] = ffma2(gOb.x, twO.x, aO[0][2]);
                    aO[0][3] = ffma2(gOb.y, twO.x, aO[0][3]);
                    aO[1][0] = ffma2(gOa.x, twO.y, aO[1][0]);
                    aO[1][1] = ffma2(gOa.y, twO.y, aO[1][1]);
                    aO[1][2] = ffma2(gOb.x, twO.y, aO[1][2]);
                    aO[1][3] = ffma2(gOb.y, twO.y, aO[1][3]);
                    A[0] -= u2f(gEa.x).x; A[1] -= u2f(gEa.y).x;
                    A[2] -= u2f(gEb.x).x; A[3] -= u2f(gEb.y).x;
                    B[0] -= u2f(gOa.x).y; B[1] -= u2f(gOa.y).y;
                    B[2] -= u2f(gOb.x).y; B[3] -= u2f(gOb.y).y;
                }
            }

            #pragma unroll
            for (int r = 0; r < 4; ++r) {
                const int h = hb + r0 + r;
                float2 pq0 = u2f(fadd2(aE[0][r], aO[0][r]));  // (C,S) @ w0
                float2 rt0 = u2f(fsub2(aE[0][r], aO[0][r]));  // (R,T) @ w0
                float2 pq1 = u2f(fadd2(aE[1][r], aO[1][r]));  // @ w1
                float2 rt1 = u2f(fsub2(aE[1][r], aO[1][r]));
                float y0  = pq0.x - pq0.y + bias_o;   // col w0
                float y1  = pq1.x - pq1.y + bias_o;   // col w0+1
                float m0  = pq0.x + pq0.y + bias_o;   // col 256-w0
                float m1  = pq1.x + pq1.y + bias_o;   // col 255-w0
                float p0  = rt0.x + rt0.y + bias_o;   // col 128-w0
                float p1  = rt1.x + rt1.y + bias_o;   // col 127-w0
                float q0  = rt0.x - rt0.y + bias_o;   // col 128+w0
                float q1  = rt1.x - rt1.y + bias_o;   // col 129+w0
                *(float2*)&yp[h * 256 + w0] = make_float2(y0, y1);
                *(float2*)&yp[h * 256 + 128 + w0] = make_float2(q0, q1);
                yp[h * 256 + (128 - w0)] = p0;
                yp[h * 256 + (127 - w0)] = p1;
                yp[h * 256 + (255 - w0)] = m1;
                if (wp) yp[h * 256 + (256 - w0)] = m0;
                if (wp == 0) {
                    yp[h * 256 + 64]  = A[r] - B[r] + bias_o;
                    yp[h * 256 + 192] = A[r] + B[r] + bias_o;
                }
            }
        }
        __syncthreads();
    }
}

// ---------------------------------------------------------------------------
extern "C" void kernel_launch(void* const* d_in, const int* in_sizes, int n_in,
                              void* d_out, int out_size) {
    const float* x    = (const float*)d_in[0];
    const float* wts  = (const float*)d_in[1];
    const float* bias = (const float*)d_in[2];
    float* out = (float*)d_out;

    cudaFuncSetAttribute(fwd_kernel, cudaFuncAttributeMaxDynamicSharedMemorySize,
                         FWD_SMEM_BYTES);
    cudaFuncSetAttribute(inv_kernel, cudaFuncAttributeMaxDynamicSharedMemorySize,
                         INV_SMEM_BYTES);

    transpose_w<<<dim3(128, 32), 256>>>(wts);
    fwd_kernel<<<Bn * CIN, 256, FWD_SMEM_BYTES>>>(x);
    mix_kernel<<<1024, 256>>>();
    inv_kernel<<<Bn * COUT, 256, INV_SMEM_BYTES>>>(bias, out);
}

// round 14
// speedup vs baseline: 2.0563x; 1.0171x over previous
#include <cuda_runtime.h>
#include <math.h>

typedef unsigned long long u64;
typedef ulonglong2 u64x2;

#define Hn   256
#define Wn   256
#define CIN  64
#define COUT 64
#define Bn   16

__device__ __forceinline__ u64 f2u(float lo, float hi) {
    u64 r; asm("mov.b64 %0, {%1,%2};" : "=l"(r) : "f"(lo), "f"(hi)); return r;
}
__device__ __forceinline__ float2 u2f(u64 v) {
    float2 r; asm("mov.b64 {%0,%1}, %2;" : "=f"(r.x), "=f"(r.y) : "l"(v)); return r;
}
__device__ __forceinline__ u64 ffma2(u64 a, u64 b, u64 c) {
    u64 d; asm("fma.rn.f32x2 %0, %1, %2, %3;" : "=l"(d) : "l"(a), "l"(b), "l"(c));
    return d;
}
__device__ __forceinline__ u64 fadd2(u64 a, u64 b) {
    u64 d; asm("add.rn.f32x2 %0, %1, %2;" : "=l"(d) : "l"(a), "l"(b));
    return d;
}
__device__ __forceinline__ u64 fsub2(u64 a, u64 b) {
    return fadd2(a, b ^ 0x8000000080000000ull);
}
__device__ __forceinline__ unsigned smem_u32(const void* p) {
    unsigned a;
    asm("{ .reg .u64 t; cvta.to.shared.u64 t, %1; cvt.u32.u64 %0, t; }"
        : "=r"(a) : "l"(p));
    return a;
}

// g_X is MODE-MAJOR: [mode][b*CIN + i].  g_S stays b-major: [bo][mode].
__device__ u64 g_X[1024 * Bn * CIN];
__device__ u64 g_S[Bn * COUT * 1024];
// Transposed weights: [mode][io]
__device__ float g_Wt[1024 * 4096];

// ---------------------------------------------------------------------------
// Weight transpose: wts[io][m] -> g_Wt[m][io]
// ---------------------------------------------------------------------------
__global__ __launch_bounds__(256) void transpose_w(const float* __restrict__ wts) {
    __shared__ float tile[32][33];
    const int tx = threadIdx.x & 31, ty = threadIdx.x >> 5;   // 32 x 8
    const int io0 = blockIdx.x * 32;
    const int m0  = blockIdx.y * 32;
    #pragma unroll
    for (int j = ty; j < 32; j += 8)
        tile[j][tx] = wts[(size_t)(io0 + j) * 1024 + m0 + tx];
    __syncthreads();
    #pragma unroll
    for (int j = ty; j < 32; j += 8)
        g_Wt[(size_t)(m0 + j) * 4096 + io0 + tx] = tile[tx][j];
}

// ---------------------------------------------------------------------------
// Forward v5 (proven): quarter-fold + cp.async pipeline.  Only the final
// g_X store indexing changed (mode-major).
// ---------------------------------------------------------------------------
#define FWD_SMEM_BYTES (65*32*8 + 256*16 + 32*256*4 + 32*65*16 + 32*8 + 32*32*8)

__global__ __launch_bounds__(256, 2) void fwd_kernel(const float* __restrict__ x) {
    extern __shared__ char smraw[];
    float2* s_cs  = (float2*)smraw;
    float4* s_t4  = (float4*)(s_cs + 65 * 32);
    float*  s_raw = (float*)(s_t4 + 256);
    u64x2*  s_xq  = (u64x2*)(s_raw + 32 * 256);
    u64*    s_x64 = (u64*)(s_xq + 32 * 65);
    u64*    s_D   = s_x64 + 32;

    const int t  = threadIdx.x;
    const int bi = blockIdx.x;
    const float* xp = x + (size_t)bi * (Hn * Wn);

    const unsigned raw_base = smem_u32(s_raw);
    {
        #pragma unroll
        for (int j = 0; j < 8; ++j) {
            int e = t + j * 256;
            const float* src = xp + e * 4;
            unsigned dst = raw_base + e * 16;
            asm volatile("cp.async.ca.shared.global [%0], [%1], 16;"
                         :: "r"(dst), "l"(src));
        }
        asm volatile("cp.async.commit_group;");
    }

    for (int idx = t; idx < 65 * 32; idx += 256) {
        int w = idx >> 5, kx = idx & 31;
        float sv, cv;
        sincospif(((w * kx) & 255) * (2.0f / 256.0f), &sv, &cv);
        s_cs[idx] = make_float2(cv, -sv);
    }
    {
        float sv, cv;
        sincospif(t * (2.0f / 256.0f), &sv, &cv);
        s_t4[t] = make_float4(cv, cv, sv, sv);
    }

    const int warp = t >> 5, lane = t & 31;
    const int kxg  = warp & 1;
    const int rg   = warp >> 1;
    const int kl   = lane & 7;
    const int rl   = lane >> 3;
    const int kx0  = kxg * 16 + kl * 2;
    const int row0 = rg * 8 + rl * 2;

    u64 X[2][2];
    X[0][0] = X[0][1] = X[1][0] = X[1][1] = 0ull;

    const u64* cs64 = (const u64*)s_cs;

    asm volatile("cp.async.wait_group 0;");
    __syncthreads();

    for (int c = 0; c < 8; ++c) {
        #pragma unroll 2
        for (int idx = t; idx < 32 * 64; idx += 256) {
            int r = idx >> 6;
            int w = idx & 63;
            const float* row = s_raw + r * 256;
            u64x2 v;
            if (w == 0) {
                float x0 = row[0], x128 = row[128];
                v.x = f2u(x0 + x128, 0.f);
                v.y = f2u(x0 - x128, 0.f);
            } else {
                float xa = row[w],       xb = row[256 - w];
                float xc = row[128 - w], xd = row[128 + w];
                v.x = f2u(xa + xb + xc + xd, xa - xb - xc + xd);
                v.y = f2u(xa + xb - xc - xd, xa - xb + xc - xd);
            }
            s_xq[r * 65 + w] = v;
        }
        if (t < 32) {
            const float* row = s_raw + t * 256;
            float a = row[64], b = row[192];
            s_x64[t] = f2u(a + b, a - b);
        }
        __syncthreads();

        if (c < 7) {
            const float* xc = xp + (size_t)(c + 1) * 32 * Wn;
            #pragma unroll
            for (int j = 0; j < 8; ++j) {
                int e = t + j * 256;
                const float* src = xc + e * 4;
                unsigned dst = raw_base + e * 16;
                asm volatile("cp.async.ca.shared.global [%0], [%1], 16;"
                             :: "r"(dst), "l"(src));
            }
            asm volatile("cp.async.commit_group;");
        }

        {
            u64 a00 = 0ull, a01 = 0ull, a10 = 0ull, a11 = 0ull;
            #pragma unroll 4
            for (int w = 0; w < 64; ++w) {
                u64x2 tw = *(const u64x2*)&cs64[w * 32 + kx0];
                u64x2 v0 = s_xq[row0 * 65 + w];
                u64x2 v1 = s_xq[(row0 + 1) * 65 + w];
                a00 = ffma2(v0.x, tw.x, a00);
                a01 = ffma2(v0.y, tw.y, a01);
                a10 = ffma2(v1.x, tw.x, a10);
                a11 = ffma2(v1.y, tw.y, a11);
            }
            {
                u64x2 tw = *(const u64x2*)&cs64[64 * 32 + kx0];
                u64 v0 = s_x64[row0];
                u64 v1 = s_x64[row0 + 1];
                a00 = ffma2(v0, tw.x, a00);
                a01 = ffma2(v0, tw.y, a01);
                a10 = ffma2(v1, tw.x, a10);
                a11 = ffma2(v1, tw.y, a11);
            }
            u64x2 p0; p0.x = a00; p0.y = a01;
            u64x2 p1; p1.x = a10; p1.y = a11;
            *(u64x2*)&s_D[row0 * 32 + kx0]       = p0;
            *(u64x2*)&s_D[(row0 + 1) * 32 + kx0] = p1;
        }
        __syncthreads();

        const int h0 = c * 32;
        #pragma unroll 4
        for (int r = 0; r < 32; ++r) {
            const int h = h0 + r;
            u64x2 dp = *(const u64x2*)&s_D[r * 32 + kx0];
            float2 d0 = u2f(dp.x), d1 = u2f(dp.y);
            u64 dq0 = f2u(d0.y, -d0.x);
            u64 dq1 = f2u(d1.y, -d1.x);
            u64x2 e0 = *(const u64x2*)&s_t4[(row0 * h) & 255];
            u64x2 e1 = *(const u64x2*)&s_t4[((row0 + 1) * h) & 255];
            X[0][0] = ffma2(dp.x, e0.x, X[0][0]);
            X[0][0] = ffma2(dq0,  e0.y, X[0][0]);
            X[0][1] = ffma2(dp.y, e0.x, X[0][1]);
            X[0][1] = ffma2(dq1,  e0.y, X[0][1]);
            X[1][0] = ffma2(dp.x, e1.x, X[1][0]);
            X[1][0] = ffma2(dq0,  e1.y, X[1][0]);
            X[1][1] = ffma2(dp.y, e1.x, X[1][1]);
            X[1][1] = ffma2(dq1,  e1.y, X[1][1]);
        }
        if (c < 7) asm volatile("cp.async.wait_group 0;");
        __syncthreads();
    }

    // mode-major store: g_X[m][bi]
    #pragma unroll
    for (int j = 0; j < 2; ++j)
        #pragma unroll
        for (int i = 0; i < 2; ++i)
            g_X[(size_t)((row0 + j) * 32 + kx0 + i) * 1024 + bi] = X[j][i];
}

// ---------------------------------------------------------------------------
// Mix: fully coalesced loads (g_Wt and mode-major g_X)
// ---------------------------------------------------------------------------
__global__ __launch_bounds__(256) void mix_kernel() {
    __shared__ float s_W[CIN * COUT];
    __shared__ u64   s_X[Bn * CIN];
    const int t = threadIdx.x;
    const int m = blockIdx.x;

    {
        const float4* wp4 = (const float4*)(g_Wt + (size_t)m * 4096);
        #pragma unroll
        for (int e = t; e < 1024; e += 256)
            ((float4*)s_W)[e] = wp4[e];
        const u64x2* xp2 = (const u64x2*)(g_X + (size_t)m * 1024);
        #pragma unroll
        for (int e = t; e < 512; e += 256)
            ((u64x2*)s_X)[e] = xp2[e];
    }
    __syncthreads();

    const int o  = t & 63;
    const int bq = t >> 6;
    u64 acc[4] = {0ull, 0ull, 0ull, 0ull};

    #pragma unroll 8
    for (int i = 0; i < CIN; ++i) {
        float wv = s_W[i * 64 + o];
        u64 wp = f2u(wv, wv);
        #pragma unroll
        for (int j = 0; j < 4; ++j)
            acc[j] = ffma2(s_X[(bq * 4 + j) * 64 + i], wp, acc[j]);
    }
    #pragma unroll
    for (int j = 0; j < 4; ++j)
        g_S[((size_t)(bq * 4 + j) * 64 + o) * 1024 + m] = acc[j];
}

// ---------------------------------------------------------------------------
// Inverse v5: 32-row super-chunks.  C1 (ky-parity folded) runs twice filling
// 32-row G buffers; C2 uses 2w x 8r thread tiles (G loads amortized); cols
// 64/192 moved to a tiny post-pass (no per-kk scalar extracts in hot loop).
// smem: ci[32][68] f2 | t4i[256] f4 | S[1024] u64 | Ga[32*34] | Gb[32*34]
//       total 47104 B -> 4 blocks/SM
// ---------------------------------------------------------------------------
#define INV_SMEM_BYTES (32*68*8 + 256*16 + 1024*8 + 2*32*34*8)

__global__ __launch_bounds__(256) void inv_kernel(const float* __restrict__ bias,
                                                  float* __restrict__ out) {
    extern __shared__ char smraw[];
    float2* s_ci  = (float2*)smraw;                 // [kk*68 + w], w in [0,64]
    float4* s_t4i = (float4*)(s_ci + 32 * 68);      // [n] = (c, s, -s, c)
    u64*    s_S   = (u64*)(s_t4i + 256);            // [ky*32 + kx], pre-scaled
    u64*    s_Ga  = s_S + 1024;                     // [kk*34 + r], r in 0..31
    u64*    s_Gb  = s_Ga + 32 * 34;                 // +128 twin rows

    const int t  = threadIdx.x;
    const int bo = blockIdx.x;
    const int o  = bo & 63;

    for (int idx = t; idx < 32 * 65; idx += 256) {
        int kk = idx / 65;
        int w  = idx - kk * 65;
        float sv, cv;
        sincospif(((kk * w) & 255) * (2.0f / 256.0f), &sv, &cv);
        s_ci[kk * 68 + w] = make_float2(cv, sv);
    }
    {
        float sv, cv;
        sincospif(t * (2.0f / 256.0f), &sv, &cv);
        s_t4i[t] = make_float4(cv, sv, -sv, cv);
    }
    for (int e = t; e < 1024; e += 256) {
        float2 v  = u2f(g_S[(size_t)bo * 1024 + e]);
        float sc  = ((e & 31) == 0 ? 1.f : 2.f) * (1.f / 65536.f);
        s_S[e] = f2u(v.x * sc, v.y * sc);
    }
    const float bias_o = bias[o];
    __syncthreads();

    // C1 mapping: lane = kx, warp r2: row pair (2r2, 2r2+1) per sub-pass
    const int kx = t & 31, r2 = t >> 5;
    // C2 mapping: wp -> cols (2wp, 2wp+1) & mirrors; rg -> 8 rows; half
    const int wp   = t & 31;
    const int w0   = wp * 2;
    const int rg   = (t >> 5) & 3;
    const int half = t >> 7;
    const int r0   = rg * 8;

    float* yp = out + (size_t)bo * (Hn * Wn);
    const u64* Gh = half ? s_Gb : s_Ga;

    for (int cp = 0; cp < 4; ++cp) {
        const int hb32 = cp * 32;

        // ---- C1 x2: fill 32 rows of Ga (low) / Gb (+128 twins)
        #pragma unroll
        for (int sub = 0; sub < 2; ++sub) {
            const int h1 = hb32 + 16 * sub + 2 * r2;
            const int h2 = h1 + 1;
            u64 aE1 = 0ull, aO1 = 0ull, aE2 = 0ull, aO2 = 0ull;
            #pragma unroll 4
            for (int ky = 0; ky < 32; ky += 2) {
                float2 sv = u2f(s_S[ky * 32 + kx]);
                u64 sxx = f2u(sv.x, sv.x);
                u64 syy = f2u(sv.y, sv.y);
                u64x2 e1 = *(const u64x2*)&s_t4i[(ky * h1) & 255];
                u64x2 e2 = *(const u64x2*)&s_t4i[(ky * h2) & 255];
                aE1 = ffma2(sxx, e1.x, aE1);
                aE1 = ffma2(syy, e1.y, aE1);
                aE2 = ffma2(sxx, e2.x, aE2);
                aE2 = ffma2(syy, e2.y, aE2);
                float2 sw = u2f(s_S[(ky + 1) * 32 + kx]);
                u64 txx = f2u(sw.x, sw.x);
                u64 tyy = f2u(sw.y, sw.y);
                u64x2 f1  = *(const u64x2*)&s_t4i[((ky + 1) * h1) & 255];
                u64x2 f2v = *(const u64x2*)&s_t4i[((ky + 1) * h2) & 255];
                aO1 = ffma2(txx, f1.x, aO1);
                aO1 = ffma2(tyy, f1.y, aO1);
                aO2 = ffma2(txx, f2v.x, aO2);
                aO2 = ffma2(tyy, f2v.y, aO2);
            }
            u64x2 ga; ga.x = fadd2(aE1, aO1); ga.y = fadd2(aE2, aO2);
            u64x2 gb; gb.x = fsub2(aE1, aO1); gb.y = fsub2(aE2, aO2);
            *(u64x2*)&s_Ga[kx * 34 + 16 * sub + 2 * r2] = ga;
            *(u64x2*)&s_Gb[kx * 34 + 16 * sub + 2 * r2] = gb;
        }
        __syncthreads();

        // ---- C2: 2w x 8r per thread, both kk-parities
        {
            u64 aE[2][8], aO[2][8];
            #pragma unroll
            for (int wv = 0; wv < 2; ++wv)
                #pragma unroll
                for (int r = 0; r < 8; ++r) { aE[wv][r] = 0ull; aO[wv][r] = 0ull; }

            #pragma unroll 2
            for (int kk = 0; kk < 32; kk += 2) {
                u64x2 twE = *(const u64x2*)&s_ci[kk * 68 + w0];
                u64x2 twO = *(const u64x2*)&s_ci[(kk + 1) * 68 + w0];
                const u64* GE = &Gh[kk * 34 + r0];
                const u64* GO = &Gh[(kk + 1) * 34 + r0];
                #pragma unroll
                for (int rr = 0; rr < 4; ++rr) {
                    u64x2 gE = *(const u64x2*)&GE[2 * rr];
                    u64x2 gO = *(const u64x2*)&GO[2 * rr];
                    aE[0][2*rr]   = ffma2(gE.x, twE.x, aE[0][2*rr]);
                    aE[0][2*rr+1] = ffma2(gE.y, twE.x, aE[0][2*rr+1]);
                    aE[1][2*rr]   = ffma2(gE.x, twE.y, aE[1][2*rr]);
                    aE[1][2*rr+1] = ffma2(gE.y, twE.y, aE[1][2*rr+1]);
                    aO[0][2*rr]   = ffma2(gO.x, twO.x, aO[0][2*rr]);
                    aO[0][2*rr+1] = ffma2(gO.y, twO.x, aO[0][2*rr+1]);
                    aO[1][2*rr]   = ffma2(gO.x, twO.y, aO[1][2*rr]);
                    aO[1][2*rr+1] = ffma2(gO.y, twO.y, aO[1][2*rr+1]);
                }
            }

            #pragma unroll
            for (int r = 0; r < 8; ++r) {
                const int h = hb32 + half * 128 + r0 + r;
                float2 pq0 = u2f(fadd2(aE[0][r], aO[0][r]));  // (C,S) @ w0
                float2 rt0 = u2f(fsub2(aE[0][r], aO[0][r]));  // (R,T) @ w0
                float2 pq1 = u2f(fadd2(aE[1][r], aO[1][r]));  // @ w0+1
                float2 rt1 = u2f(fsub2(aE[1][r], aO[1][r]));
                float y0  = pq0.x - pq0.y + bias_o;   // col w0
                float y1  = pq1.x - pq1.y + bias_o;   // col w0+1
                float m0  = pq0.x + pq0.y + bias_o;   // col 256-w0
                float m1  = pq1.x + pq1.y + bias_o;   // col 255-w0
                float p0  = rt0.x + rt0.y + bias_o;   // col 128-w0
                float p1  = rt1.x + rt1.y + bias_o;   // col 127-w0
                float q0  = rt0.x - rt0.y + bias_o;   // col 128+w0
                float q1  = rt1.x - rt1.y + bias_o;   // col 129+w0
                *(float2*)&yp[h * 256 + w0] = make_float2(y0, y1);
                *(float2*)&yp[h * 256 + 128 + w0] = make_float2(q0, q1);
                yp[h * 256 + (128 - w0)] = p0;
                yp[h * 256 + (127 - w0)] = p1;
                yp[h * 256 + (255 - w0)] = m1;
                if (wp) yp[h * 256 + (256 - w0)] = m0;
            }
        }

        // ---- cols 64 / 192: threads 0..63, one (row, half) each
        if (t < 64) {
            const u64* G = (t >= 32) ? s_Gb : s_Ga;
            const int r = t & 31;
            float A = 0.f, B = 0.f;
            #pragma unroll
            for (int kk = 0; kk < 32; kk += 4) {
                A += u2f(G[kk * 34 + r]).x;
                A -= u2f(G[(kk + 2) * 34 + r]).x;
                B += u2f(G[(kk + 1) * 34 + r]).y;
                B -= u2f(G[(kk + 3) * 34 + r]).y;
            }
            const int h = hb32 + ((t >= 32) ? 128 : 0) + r;
            yp[h * 256 + 64]  = A - B + bias_o;
            yp[h * 256 + 192] = A + B + bias_o;
        }
        __syncthreads();
    }
}

// ---------------------------------------------------------------------------
extern "C" void kernel_launch(void* const* d_in, const int* in_sizes, int n_in,
                              void* d_out, int out_size) {
    const float* x    = (const float*)d_in[0];
    const float* wts  = (const float*)d_in[1];
    const float* bias = (const float*)d_in[2];
    float* out = (float*)d_out;

    cudaFuncSetAttribute(fwd_kernel, cudaFuncAttributeMaxDynamicSharedMemorySize,
                         FWD_SMEM_BYTES);
    cudaFuncSetAttribute(inv_kernel, cudaFuncAttributeMaxDynamicSharedMemorySize,
                         INV_SMEM_BYTES);

    transpose_w<<<dim3(128, 32), 256>>>(wts);
    fwd_kernel<<<Bn * CIN, 256, FWD_SMEM_BYTES>>>(x);
    mix_kernel<<<1024, 256>>>();
    inv_kernel<<<Bn * COUT, 256, INV_SMEM_BYTES>>>(bias, out);
}